// round 1
// baseline (speedup 1.0000x reference)
#include <cuda_runtime.h>
#include <cuda_bf16.h>
#include <mma.h>

using namespace nvcuda;

// Problem constants (shapes fixed by the dataset)
constexpr int T  = 8192;      // tokens = B*S = 4*2048
constexpr int D  = 1024;      // hidden dim
constexpr int F  = 4096;      // ffn dim
constexpr int E  = 8;         // experts
constexpr int TK = T * 2;     // total (token, expert) rows = T * top_k

// GEMM tiling
constexpr int BM = 64, BN = 64, BK = 16;
constexpr int LDAS = BK + 4;  // 20 (mult of 4 for wmma ld)
constexpr int LDBS = BN + 4;  // 68
constexpr int LDCS = BN + 4;  // 68

// ---------------- device scratch (static; no allocations) ----------------
__device__ int   g_top_e[TK];
__device__ float g_top_w[TK];
__device__ int   g_slot[TK];          // (token,k) -> global row slot
__device__ int   g_tok[TK];           // global row slot -> token
__device__ int   g_off[E + 1];        // expert row offsets (prefix sum)
__device__ float g_buf1[(size_t)TK * F];   // gate output, then h = silu(g)*u
__device__ float g_buf2[(size_t)TK * F];   // up output, then reused as down output [TK][D]

// ---------------- router: logits -> softmax -> top-2 ----------------
__global__ void router_kernel(const float* __restrict__ x,
                              const float* __restrict__ rw) {
    __shared__ float rws[E * D];  // transposed: rws[e*D + d]
    for (int i = threadIdx.x; i < E * D; i += blockDim.x)
        rws[i] = rw[(i & (D - 1)) * E + (i >> 10)];
    __syncthreads();

    int wid = threadIdx.x >> 5, lane = threadIdx.x & 31;
    int t = blockIdx.x * 8 + wid;
    const float* xr = x + (size_t)t * D;

    float acc[E];
#pragma unroll
    for (int e = 0; e < E; e++) acc[e] = 0.f;
    for (int j = 0; j < D / 32; j++) {
        int d = j * 32 + lane;
        float xv = xr[d];
#pragma unroll
        for (int e = 0; e < E; e++) acc[e] += xv * rws[e * D + d];
    }
#pragma unroll
    for (int e = 0; e < E; e++)
#pragma unroll
        for (int o = 16; o > 0; o >>= 1)
            acc[e] += __shfl_xor_sync(0xffffffffu, acc[e], o);

    if (lane == 0) {
        float m = acc[0];
#pragma unroll
        for (int e = 1; e < E; e++) m = fmaxf(m, acc[e]);
        float p[E], s = 0.f;
#pragma unroll
        for (int e = 0; e < E; e++) { p[e] = expf(acc[e] - m); s += p[e]; }
        float inv = 1.f / s;
        // top-1: strict > keeps lowest index on ties (matches jax.lax.top_k)
        int e0 = 0;
#pragma unroll
        for (int e = 1; e < E; e++) if (acc[e] > acc[e0]) e0 = e;
        int e1 = (e0 == 0) ? 1 : 0;
#pragma unroll
        for (int e = 0; e < E; e++) if (e != e0 && acc[e] > acc[e1]) e1 = e;
        g_top_e[2 * t]     = e0;
        g_top_e[2 * t + 1] = e1;
        g_top_w[2 * t]     = p[e0] * inv;
        g_top_w[2 * t + 1] = p[e1] * inv;
    }
}

// ---------------- deterministic per-expert token lists ----------------
__global__ void build_lists_kernel() {
    __shared__ int cnts[E];
    int wid = threadIdx.x >> 5, lane = threadIdx.x & 31;
    if (wid < E) {
        int e = wid, c = 0;
        for (int base = 0; base < T; base += 32) {
            int t = base + lane;
            bool m = (g_top_e[2 * t] == e) || (g_top_e[2 * t + 1] == e);
            c += __popc(__ballot_sync(0xffffffffu, m));
        }
        if (lane == 0) cnts[e] = c;
    }
    __syncthreads();
    if (threadIdx.x == 0) {
        int s = 0;
        for (int e = 0; e < E; e++) { g_off[e] = s; s += cnts[e]; }
        g_off[E] = s;
        for (int e = 0; e < E; e++) cnts[e] = g_off[e];  // running positions
    }
    __syncthreads();
    if (wid < E) {
        int e = wid;
        int pos = cnts[e];
        for (int base = 0; base < T; base += 32) {
            int t = base + lane;
            bool m0 = (g_top_e[2 * t] == e);
            bool m1 = (g_top_e[2 * t + 1] == e);
            bool m = m0 || m1;
            unsigned mask = __ballot_sync(0xffffffffu, m);
            if (m) {
                int idx = pos + __popc(mask & ((1u << lane) - 1));
                g_tok[idx] = t;
                g_slot[2 * t + (m0 ? 0 : 1)] = idx;
            }
            pos += __popc(mask);
        }
    }
}

// ---------------- grouped GEMM, tf32x3 (fp32-accurate) ----------------
// C[off+r, :] = A_row(r) @ W_e     with A gathered via tok (or contiguous if tok==nullptr)
__global__ __launch_bounds__(256) void gemm_tf32x3(
    const float* __restrict__ A, int lda,
    const int* __restrict__ tok,
    const float* __restrict__ Wfull, size_t wstride,
    int Kdim, int Ndim,
    float* __restrict__ Cbase, int ldc)
{
    int e   = blockIdx.z;
    int off = g_off[e];
    int cnt = g_off[e + 1] - off;
    int m0  = blockIdx.y * BM;
    if (m0 >= cnt) return;
    int n0 = blockIdx.x * BN;
    const float* W = Wfull + (size_t)e * wstride;

    __shared__ float As_hi[BM][LDAS], As_lo[BM][LDAS];
    __shared__ float Bs_hi[BK][LDBS], Bs_lo[BK][LDBS];
    __shared__ const float* Arow[BM];
    __shared__ float Cs[BM][LDCS];

    int tid = threadIdx.x;
    if (tid < BM) {
        int r  = m0 + tid;
        int rr = (r < cnt) ? r : 0;
        int gr = tok ? tok[off + rr] : (off + rr);
        Arow[tid] = A + (size_t)gr * lda;
    }
    __syncthreads();

    int wid = tid >> 5;
    int wm  = wid & 3;    // 4 warps along M (16 rows each)
    int wn  = wid >> 2;   // 2 warps along N (32 cols each)

    wmma::fragment<wmma::accumulator, 16, 16, 8, float> acc0, acc1;
    wmma::fill_fragment(acc0, 0.f);
    wmma::fill_fragment(acc1, 0.f);

    int ar = tid >> 2,  ac = (tid & 3) * 4;    // A tile load coords (64x16)
    int br = tid >> 4,  bc = (tid & 15) * 4;   // B tile load coords (16x64)
    const float* aptr = Arow[ar] + ac;

    for (int k0 = 0; k0 < Kdim; k0 += BK) {
        float4 av = *(const float4*)(aptr + k0);
        float4 bv = *(const float4*)(W + (size_t)(k0 + br) * Ndim + n0 + bc);

        __syncthreads();  // previous iteration's consumers done

        float4 ah, al, bh, bl;
        ah.x = wmma::__float_to_tf32(av.x); al.x = wmma::__float_to_tf32(av.x - ah.x);
        ah.y = wmma::__float_to_tf32(av.y); al.y = wmma::__float_to_tf32(av.y - ah.y);
        ah.z = wmma::__float_to_tf32(av.z); al.z = wmma::__float_to_tf32(av.z - ah.z);
        ah.w = wmma::__float_to_tf32(av.w); al.w = wmma::__float_to_tf32(av.w - ah.w);
        bh.x = wmma::__float_to_tf32(bv.x); bl.x = wmma::__float_to_tf32(bv.x - bh.x);
        bh.y = wmma::__float_to_tf32(bv.y); bl.y = wmma::__float_to_tf32(bv.y - bh.y);
        bh.z = wmma::__float_to_tf32(bv.z); bl.z = wmma::__float_to_tf32(bv.z - bh.z);
        bh.w = wmma::__float_to_tf32(bv.w); bl.w = wmma::__float_to_tf32(bv.w - bh.w);

        *(float4*)&As_hi[ar][ac] = ah;
        *(float4*)&As_lo[ar][ac] = al;
        *(float4*)&Bs_hi[br][bc] = bh;
        *(float4*)&Bs_lo[br][bc] = bl;
        __syncthreads();

#pragma unroll
        for (int kk = 0; kk < BK; kk += 8) {
            wmma::fragment<wmma::matrix_a, 16, 16, 8, wmma::precision::tf32, wmma::row_major> fa_h, fa_l;
            wmma::load_matrix_sync(fa_h, &As_hi[wm * 16][kk], LDAS);
            wmma::load_matrix_sync(fa_l, &As_lo[wm * 16][kk], LDAS);
            wmma::fragment<wmma::matrix_b, 16, 16, 8, wmma::precision::tf32, wmma::row_major> fb_h0, fb_l0, fb_h1, fb_l1;
            wmma::load_matrix_sync(fb_h0, &Bs_hi[kk][wn * 32],      LDBS);
            wmma::load_matrix_sync(fb_l0, &Bs_lo[kk][wn * 32],      LDBS);
            wmma::load_matrix_sync(fb_h1, &Bs_hi[kk][wn * 32 + 16], LDBS);
            wmma::load_matrix_sync(fb_l1, &Bs_lo[kk][wn * 32 + 16], LDBS);
            // tf32x3: hi*hi + hi*lo + lo*hi (lo*lo dropped, ~2^-22)
            wmma::mma_sync(acc0, fa_h, fb_h0, acc0);
            wmma::mma_sync(acc0, fa_h, fb_l0, acc0);
            wmma::mma_sync(acc0, fa_l, fb_h0, acc0);
            wmma::mma_sync(acc1, fa_h, fb_h1, acc1);
            wmma::mma_sync(acc1, fa_h, fb_l1, acc1);
            wmma::mma_sync(acc1, fa_l, fb_h1, acc1);
        }
    }

    __syncthreads();
    wmma::store_matrix_sync(&Cs[wm * 16][wn * 32],      acc0, LDCS, wmma::mem_row_major);
    wmma::store_matrix_sync(&Cs[wm * 16][wn * 32 + 16], acc1, LDCS, wmma::mem_row_major);
    __syncthreads();

    for (int q = tid; q < BM * (BN / 4); q += 256) {
        int r = q >> 4;
        int c = (q & 15) * 4;
        if (m0 + r < cnt) {
            *(float4*)&Cbase[(size_t)(off + m0 + r) * ldc + n0 + c] = *(const float4*)&Cs[r][c];
        }
    }
}

// ---------------- h = silu(gate) * up (in place into g_buf1) ----------------
__global__ void silu_mul_kernel() {
    size_t n = (size_t)TK * F / 4;
    float4* g = (float4*)g_buf1;
    const float4* u = (const float4*)g_buf2;
    for (size_t i = (size_t)blockIdx.x * blockDim.x + threadIdx.x; i < n;
         i += (size_t)gridDim.x * blockDim.x) {
        float4 gv = g[i], uv = u[i];
        gv.x = gv.x / (1.f + expf(-gv.x)) * uv.x;
        gv.y = gv.y / (1.f + expf(-gv.y)) * uv.y;
        gv.z = gv.z / (1.f + expf(-gv.z)) * uv.z;
        gv.w = gv.w / (1.f + expf(-gv.w)) * uv.w;
        g[i] = gv;
    }
}

// ---------------- weighted combine: out[t] = w0*d[slot0] + w1*d[slot1] ----------------
__global__ void combine_kernel(float* __restrict__ out) {
    int t = blockIdx.x;
    float w0 = g_top_w[2 * t], w1 = g_top_w[2 * t + 1];
    const float* r0 = g_buf2 + (size_t)g_slot[2 * t] * D;
    const float* r1 = g_buf2 + (size_t)g_slot[2 * t + 1] * D;
    int c = threadIdx.x * 4;
    float4 a = *(const float4*)(r0 + c);
    float4 b = *(const float4*)(r1 + c);
    float4 o;
    o.x = w0 * a.x + w1 * b.x;
    o.y = w0 * a.y + w1 * b.y;
    o.z = w0 * a.z + w1 * b.z;
    o.w = w0 * a.w + w1 * b.w;
    *(float4*)(out + (size_t)t * D + c) = o;
}

// ---------------- launch ----------------
extern "C" void kernel_launch(void* const* d_in, const int* in_sizes, int n_in,
                              void* d_out, int out_size) {
    const float* x  = (const float*)d_in[0];  // [T, D]
    const float* rw = (const float*)d_in[1];  // [D, E]
    const float* gw = (const float*)d_in[2];  // [E, D, F]
    const float* uw = (const float*)d_in[3];  // [E, D, F]
    const float* dw = (const float*)d_in[4];  // [E, F, D]
    float* out = (float*)d_out;               // [T, D]

    void *p1, *p2, *ptok;
    cudaGetSymbolAddress(&p1, g_buf1);
    cudaGetSymbolAddress(&p2, g_buf2);
    cudaGetSymbolAddress(&ptok, g_tok);

    router_kernel<<<T / 8, 256>>>(x, rw);
    build_lists_kernel<<<1, 256>>>();

    dim3 g1(F / BN, T / BM, E);   // (64, 128, 8)
    gemm_tf32x3<<<g1, 256>>>(x, D, (const int*)ptok, gw, (size_t)D * F, D, F,
                             (float*)p1, F);
    gemm_tf32x3<<<g1, 256>>>(x, D, (const int*)ptok, uw, (size_t)D * F, D, F,
                             (float*)p2, F);

    silu_mul_kernel<<<65536, 256>>>();

    dim3 g2(D / BN, T / BM, E);   // (16, 128, 8)
    gemm_tf32x3<<<g2, 256>>>((const float*)p1, F, nullptr, dw, (size_t)F * D, F, D,
                             (float*)p2, D);

    combine_kernel<<<T, 256>>>(out);
}

// round 3
// speedup vs baseline: 4.1185x; 4.1185x over previous
#include <cuda_runtime.h>
#include <cuda_bf16.h>
#include <cstdint>

// ---------------- problem constants ----------------
constexpr int T  = 8192;
constexpr int D  = 1024;
constexpr int F  = 4096;
constexpr int E  = 8;
constexpr int TK = T * 2;

// ---------------- device scratch ----------------
__device__ int   g_top_e[TK];
__device__ float g_top_w[TK];
__device__ int   g_slot[TK];
__device__ int   g_tok[TK];
__device__ int   g_off[E + 1];

__device__ __nv_bfloat16 g_xhi[(size_t)T * D];
__device__ __nv_bfloat16 g_xlo[(size_t)T * D];
__device__ __nv_bfloat16 g_wgu_hi[(size_t)E * 2 * F * D];   // [e][n'=2f+b][k<D]
__device__ __nv_bfloat16 g_wgu_lo[(size_t)E * 2 * F * D];
__device__ __nv_bfloat16 g_wd_hi[(size_t)E * D * F];        // [e][n<D][k<F]
__device__ __nv_bfloat16 g_wd_lo[(size_t)E * D * F];
__device__ __nv_bfloat16 g_hhi[(size_t)TK * F];
__device__ __nv_bfloat16 g_hlo[(size_t)TK * F];
__device__ float         g_obuf[(size_t)TK * D];

// ---------------- helpers ----------------
__device__ __forceinline__ uint32_t smem_u32(const void* p) {
    uint32_t a;
    asm("{ .reg .u64 t; cvta.to.shared.u64 t, %1; cvt.u32.u64 %0, t; }" : "=r"(a) : "l"(p));
    return a;
}
__device__ __forceinline__ void cpa16(uint32_t s, const void* g) {
    asm volatile("cp.async.cg.shared.global [%0], [%1], 16;" :: "r"(s), "l"(g));
}
__device__ __forceinline__ void ldsm4(uint32_t* r, uint32_t addr) {
    asm volatile("ldmatrix.sync.aligned.m8n8.x4.shared.b16 {%0,%1,%2,%3}, [%4];"
        : "=r"(r[0]), "=r"(r[1]), "=r"(r[2]), "=r"(r[3]) : "r"(addr));
}
__device__ __forceinline__ void mma_bf16(float* d, const uint32_t* a, const uint32_t* b) {
    asm volatile("mma.sync.aligned.m16n8k16.row.col.f32.bf16.bf16.f32 "
        "{%0,%1,%2,%3}, {%4,%5,%6,%7}, {%8,%9}, {%0,%1,%2,%3};"
        : "+f"(d[0]), "+f"(d[1]), "+f"(d[2]), "+f"(d[3])
        : "r"(a[0]), "r"(a[1]), "r"(a[2]), "r"(a[3]), "r"(b[0]), "r"(b[1]));
}

// ---------------- router ----------------
__global__ void router_kernel(const float* __restrict__ x, const float* __restrict__ rw) {
    __shared__ float rws[E * D];
    for (int i = threadIdx.x; i < E * D; i += blockDim.x)
        rws[i] = rw[(i & (D - 1)) * E + (i >> 10)];
    __syncthreads();
    int wid = threadIdx.x >> 5, lane = threadIdx.x & 31;
    int t = blockIdx.x * 8 + wid;
    const float* xr = x + (size_t)t * D;
    float acc[E];
#pragma unroll
    for (int e = 0; e < E; e++) acc[e] = 0.f;
    for (int j = 0; j < D / 32; j++) {
        int d = j * 32 + lane;
        float xv = xr[d];
#pragma unroll
        for (int e = 0; e < E; e++) acc[e] += xv * rws[e * D + d];
    }
#pragma unroll
    for (int e = 0; e < E; e++)
#pragma unroll
        for (int o = 16; o > 0; o >>= 1)
            acc[e] += __shfl_xor_sync(0xffffffffu, acc[e], o);
    if (lane == 0) {
        float m = acc[0];
#pragma unroll
        for (int e = 1; e < E; e++) m = fmaxf(m, acc[e]);
        float p[E], s = 0.f;
#pragma unroll
        for (int e = 0; e < E; e++) { p[e] = expf(acc[e] - m); s += p[e]; }
        float inv = 1.f / s;
        int e0 = 0;
#pragma unroll
        for (int e = 1; e < E; e++) if (acc[e] > acc[e0]) e0 = e;
        int e1 = (e0 == 0) ? 1 : 0;
#pragma unroll
        for (int e = 0; e < E; e++) if (e != e0 && acc[e] > acc[e1]) e1 = e;
        g_top_e[2 * t] = e0; g_top_e[2 * t + 1] = e1;
        g_top_w[2 * t] = p[e0] * inv; g_top_w[2 * t + 1] = p[e1] * inv;
    }
}

// ---------------- per-expert token lists ----------------
__global__ void build_lists_kernel() {
    __shared__ int cnts[E];
    int wid = threadIdx.x >> 5, lane = threadIdx.x & 31;
    if (wid < E) {
        int e = wid, c = 0;
        for (int base = 0; base < T; base += 32) {
            int t = base + lane;
            bool m = (g_top_e[2 * t] == e) || (g_top_e[2 * t + 1] == e);
            c += __popc(__ballot_sync(0xffffffffu, m));
        }
        if (lane == 0) cnts[e] = c;
    }
    __syncthreads();
    if (threadIdx.x == 0) {
        int s = 0;
        for (int e = 0; e < E; e++) { g_off[e] = s; s += cnts[e]; }
        g_off[E] = s;
        for (int e = 0; e < E; e++) cnts[e] = g_off[e];
    }
    __syncthreads();
    if (wid < E) {
        int e = wid, pos = cnts[e];
        for (int base = 0; base < T; base += 32) {
            int t = base + lane;
            bool m0 = (g_top_e[2 * t] == e);
            bool m1 = (g_top_e[2 * t + 1] == e);
            bool m = m0 || m1;
            unsigned mask = __ballot_sync(0xffffffffu, m);
            if (m) {
                int idx = pos + __popc(mask & ((1u << lane) - 1));
                g_tok[idx] = t;
                g_slot[2 * t + (m0 ? 0 : 1)] = idx;
            }
            pos += __popc(mask);
        }
    }
}

// ---------------- prep kernels ----------------
__global__ void xsplit_kernel(const float* __restrict__ x) {
    size_t i = (size_t)blockIdx.x * blockDim.x + threadIdx.x;
    float4 v = ((const float4*)x)[i];
    __nv_bfloat16 h[4], l[4];
    float vv[4] = {v.x, v.y, v.z, v.w};
#pragma unroll
    for (int q = 0; q < 4; q++) {
        h[q] = __float2bfloat16(vv[q]);
        l[q] = __float2bfloat16(vv[q] - __bfloat162float(h[q]));
    }
    *(uint2*)&g_xhi[i * 4] = *(uint2*)h;
    *(uint2*)&g_xlo[i * 4] = *(uint2*)l;
}

__global__ void wsplit_gu_kernel(const float* __restrict__ gw, const float* __restrict__ uw) {
    int e = blockIdx.z;
    int f0 = blockIdx.x * 32, k0 = blockIdx.y * 32;
    __shared__ float sg[32][33], su[32][33];
    int tx = threadIdx.x & 31, ty = threadIdx.x >> 5;
    const float* gs = gw + ((size_t)e * D + k0) * F + f0;
    const float* us = uw + ((size_t)e * D + k0) * F + f0;
#pragma unroll
    for (int i = 0; i < 32; i += 8) {
        sg[ty + i][tx] = gs[(size_t)(ty + i) * F + tx];
        su[ty + i][tx] = us[(size_t)(ty + i) * F + tx];
    }
    __syncthreads();
#pragma unroll
    for (int i = 0; i < 32; i += 8) {
        int fr = ty + i;
        float vg = sg[tx][fr];
        float vu = su[tx][fr];
        size_t rg = ((size_t)e * 2 * F + 2 * (f0 + fr)) * D + k0 + tx;
        size_t ru = ((size_t)e * 2 * F + 2 * (f0 + fr) + 1) * D + k0 + tx;
        __nv_bfloat16 hg = __float2bfloat16(vg);
        __nv_bfloat16 hu = __float2bfloat16(vu);
        g_wgu_hi[rg] = hg; g_wgu_lo[rg] = __float2bfloat16(vg - __bfloat162float(hg));
        g_wgu_hi[ru] = hu; g_wgu_lo[ru] = __float2bfloat16(vu - __bfloat162float(hu));
    }
}

__global__ void wsplit_d_kernel(const float* __restrict__ dw) {
    int e = blockIdx.z;
    int n0 = blockIdx.x * 32, k0 = blockIdx.y * 32;
    __shared__ float s[32][33];
    int tx = threadIdx.x & 31, ty = threadIdx.x >> 5;
    const float* src = dw + ((size_t)e * F + k0) * D + n0;
#pragma unroll
    for (int i = 0; i < 32; i += 8)
        s[ty + i][tx] = src[(size_t)(ty + i) * D + tx];
    __syncthreads();
#pragma unroll
    for (int i = 0; i < 32; i += 8) {
        int nr = ty + i;
        float v = s[tx][nr];
        size_t r = ((size_t)e * D + n0 + nr) * F + k0 + tx;
        __nv_bfloat16 h = __float2bfloat16(v);
        g_wd_hi[r] = h; g_wd_lo[r] = __float2bfloat16(v - __bfloat162float(h));
    }
}

// ---------------- grouped GEMM, bf16x3 via mma.sync ----------------
// C[m,n] = sum_k A[m,k] * W[n,k]
// MODE 0: A = gathered x rows [*,1024], W = g_wgu [8192,1024], epilogue silu*up -> h bf16 hi/lo
// MODE 1: A = h rows [*,4096],         W = g_wd  [1024,4096], epilogue fp32 -> g_obuf
// Tiles: BM=128, BN=128, BK=32. 512 threads = 16 warps (4x4), warp tile 32x32.
// Shared: per stage Ahi|Alo|Bhi|Blo, each 128 rows x 80B (64B data + 16B pad). 2 stages.
constexpr int ROWB = 80;
constexpr int MATB = 128 * ROWB;     // 10240
constexpr int STGB = 4 * MATB;       // 40960
constexpr int GEMM_SMEM = 2 * STGB;  // 81920

template <int MODE>
__global__ __launch_bounds__(512) void gemm_mma() {
    constexpr int KD = MODE ? 4096 : 1024;
    constexpr int S  = KD / 32;

    int e   = blockIdx.z;
    int off = g_off[e], cnt = g_off[e + 1] - off;
    int m0  = blockIdx.x * 128;
    if (m0 >= cnt) return;
    int n0  = blockIdx.y * 128;

    extern __shared__ char smem[];
    uint32_t sb = smem_u32(smem);
    int tid = threadIdx.x, wid = tid >> 5, lane = tid & 31;
    int wm = wid & 3, wn = wid >> 2;

    const __nv_bfloat16* Ahi = MODE ? g_hhi : g_xhi;
    const __nv_bfloat16* Alo = MODE ? g_hlo : g_xlo;
    const __nv_bfloat16* Whi = (MODE ? g_wd_hi : g_wgu_hi) + (size_t)e * (MODE ? (size_t)D * F : (size_t)2 * F * D);
    const __nv_bfloat16* Wlo = (MODE ? g_wd_lo : g_wgu_lo) + (size_t)e * (MODE ? (size_t)D * F : (size_t)2 * F * D);

    // per-thread load assignment: row = tid/4 (0..127), 16B chunk = tid%4
    int lrow = tid >> 2, lc = tid & 3;
    int rr = (m0 + lrow < cnt) ? lrow : 0;
    int gr = MODE ? (off + m0 + rr) : g_tok[off + m0 + rr];
    const __nv_bfloat16* a_hi = Ahi + (size_t)gr * KD + lc * 8;
    const __nv_bfloat16* a_lo = Alo + (size_t)gr * KD + lc * 8;
    const __nv_bfloat16* b_hi = Whi + (size_t)(n0 + lrow) * KD + lc * 8;
    const __nv_bfloat16* b_lo = Wlo + (size_t)(n0 + lrow) * KD + lc * 8;
    uint32_t ldoff = (uint32_t)(lrow * ROWB + lc * 16);

    // ldmatrix base offsets (within a matrix tile)
    uint32_t aRow[2], bRow[2];
#pragma unroll
    for (int mt = 0; mt < 2; mt++) {
        int row = wm * 32 + mt * 16 + (lane & 15);
        aRow[mt] = (uint32_t)(row * ROWB + (lane >> 4) * 16);
    }
#pragma unroll
    for (int p = 0; p < 2; p++) {
        int nrow = wn * 32 + p * 16 + (lane & 7) + ((lane >> 4) << 3);
        bRow[p] = (uint32_t)(nrow * ROWB + ((lane >> 3) & 1) * 16);
    }

    float acc[2][4][4];
#pragma unroll
    for (int a = 0; a < 2; a++)
#pragma unroll
        for (int b = 0; b < 4; b++)
#pragma unroll
            for (int c = 0; c < 4; c++) acc[a][b][c] = 0.f;

    // prologue: stage 0
    {
        uint32_t base = sb;
        cpa16(base + ldoff,             a_hi);
        cpa16(base + MATB + ldoff,      a_lo);
        cpa16(base + 2 * MATB + ldoff,  b_hi);
        cpa16(base + 3 * MATB + ldoff,  b_lo);
        asm volatile("cp.async.commit_group;" ::: "memory");
    }

    for (int s = 0; s < S; s++) {
        if (s + 1 < S) {
            int k = (s + 1) * 32;
            uint32_t base = sb + ((s + 1) & 1) * STGB;
            cpa16(base + ldoff,            a_hi + k);
            cpa16(base + MATB + ldoff,     a_lo + k);
            cpa16(base + 2 * MATB + ldoff, b_hi + k);
            cpa16(base + 3 * MATB + ldoff, b_lo + k);
            asm volatile("cp.async.commit_group;" ::: "memory");
            asm volatile("cp.async.wait_group 1;" ::: "memory");
        } else {
            asm volatile("cp.async.wait_group 0;" ::: "memory");
        }
        __syncthreads();

        uint32_t base = sb + (s & 1) * STGB;
#pragma unroll
        for (int kk = 0; kk < 2; kk++) {
            uint32_t ah[2][4], al[2][4], bh[2][4], bl[2][4];
            ldsm4(ah[0], base + aRow[0] + kk * 32);
            ldsm4(ah[1], base + aRow[1] + kk * 32);
            ldsm4(al[0], base + MATB + aRow[0] + kk * 32);
            ldsm4(al[1], base + MATB + aRow[1] + kk * 32);
            ldsm4(bh[0], base + 2 * MATB + bRow[0] + kk * 32);
            ldsm4(bh[1], base + 2 * MATB + bRow[1] + kk * 32);
            ldsm4(bl[0], base + 3 * MATB + bRow[0] + kk * 32);
            ldsm4(bl[1], base + 3 * MATB + bRow[1] + kk * 32);
#pragma unroll
            for (int mt = 0; mt < 2; mt++)
#pragma unroll
                for (int nt = 0; nt < 4; nt++) {
                    const uint32_t* ph = &bh[nt >> 1][(nt & 1) * 2];
                    const uint32_t* pl = &bl[nt >> 1][(nt & 1) * 2];
                    mma_bf16(acc[mt][nt], ah[mt], ph);   // hi*hi
                    mma_bf16(acc[mt][nt], ah[mt], pl);   // hi*lo
                    mma_bf16(acc[mt][nt], al[mt], ph);   // lo*hi
                }
        }
        __syncthreads();
    }

    // ---------------- epilogue ----------------
#pragma unroll
    for (int mt = 0; mt < 2; mt++) {
        int local0 = wm * 32 + mt * 16 + (lane >> 2);
        int local1 = local0 + 8;
        bool v0 = (m0 + local0) < cnt;
        bool v1 = (m0 + local1) < cnt;
        size_t s0 = (size_t)(off + m0 + local0);
        size_t s1 = (size_t)(off + m0 + local1);
        if (MODE == 0) {
#pragma unroll
            for (int nt = 0; nt < 4; nt++) {
                int f = ((n0 + wn * 32 + nt * 8) >> 1) + (lane & 3);
                float g0 = acc[mt][nt][0], u0 = acc[mt][nt][1];
                float g1 = acc[mt][nt][2], u1 = acc[mt][nt][3];
                float h0 = g0 / (1.f + expf(-g0)) * u0;
                float h1 = g1 / (1.f + expf(-g1)) * u1;
                if (v0) {
                    __nv_bfloat16 hh = __float2bfloat16(h0);
                    g_hhi[s0 * F + f] = hh;
                    g_hlo[s0 * F + f] = __float2bfloat16(h0 - __bfloat162float(hh));
                }
                if (v1) {
                    __nv_bfloat16 hh = __float2bfloat16(h1);
                    g_hhi[s1 * F + f] = hh;
                    g_hlo[s1 * F + f] = __float2bfloat16(h1 - __bfloat162float(hh));
                }
            }
        } else {
#pragma unroll
            for (int nt = 0; nt < 4; nt++) {
                int col = n0 + wn * 32 + nt * 8 + (lane & 3) * 2;
                if (v0) *(float2*)&g_obuf[s0 * D + col] = make_float2(acc[mt][nt][0], acc[mt][nt][1]);
                if (v1) *(float2*)&g_obuf[s1 * D + col] = make_float2(acc[mt][nt][2], acc[mt][nt][3]);
            }
        }
    }
}

// ---------------- combine ----------------
__global__ void combine_kernel(float* __restrict__ out) {
    int t = blockIdx.x;
    float w0 = g_top_w[2 * t], w1 = g_top_w[2 * t + 1];
    const float* r0 = g_obuf + (size_t)g_slot[2 * t] * D;
    const float* r1 = g_obuf + (size_t)g_slot[2 * t + 1] * D;
    int c = threadIdx.x * 4;
    float4 a = *(const float4*)(r0 + c);
    float4 b = *(const float4*)(r1 + c);
    float4 o;
    o.x = w0 * a.x + w1 * b.x;
    o.y = w0 * a.y + w1 * b.y;
    o.z = w0 * a.z + w1 * b.z;
    o.w = w0 * a.w + w1 * b.w;
    *(float4*)(out + (size_t)t * D + c) = o;
}

// ---------------- launch ----------------
extern "C" void kernel_launch(void* const* d_in, const int* in_sizes, int n_in,
                              void* d_out, int out_size) {
    const float* x  = (const float*)d_in[0];
    const float* rw = (const float*)d_in[1];
    const float* gw = (const float*)d_in[2];
    const float* uw = (const float*)d_in[3];
    const float* dw = (const float*)d_in[4];
    float* out = (float*)d_out;

    cudaFuncSetAttribute(gemm_mma<0>, cudaFuncAttributeMaxDynamicSharedMemorySize, GEMM_SMEM);
    cudaFuncSetAttribute(gemm_mma<1>, cudaFuncAttributeMaxDynamicSharedMemorySize, GEMM_SMEM);

    router_kernel<<<T / 8, 256>>>(x, rw);
    build_lists_kernel<<<1, 256>>>();
    xsplit_kernel<<<(T * D / 4) / 256, 256>>>(x);
    wsplit_gu_kernel<<<dim3(F / 32, D / 32, E), 256>>>(gw, uw);
    wsplit_d_kernel<<<dim3(D / 32, F / 32, E), 256>>>(dw);

    gemm_mma<0><<<dim3(64, 2 * F / 128, E), 512, GEMM_SMEM>>>();
    gemm_mma<1><<<dim3(64, D / 128, E), 512, GEMM_SMEM>>>();

    combine_kernel<<<T, 256>>>(out);
}

// round 4
// speedup vs baseline: 5.2360x; 1.2713x over previous
#include <cuda_runtime.h>
#include <cuda_fp16.h>
#include <cstdint>

// ---------------- problem constants ----------------
constexpr int T  = 8192;
constexpr int D  = 1024;
constexpr int F  = 4096;
constexpr int E  = 8;
constexpr int TK = T * 2;

// ---------------- device scratch ----------------
__device__ int   g_top_e[TK];
__device__ float g_top_w[TK];
__device__ int   g_slot[TK];
__device__ int   g_tok[TK];
__device__ int   g_off[E + 1];

__device__ __half g_xhi[(size_t)T * D];
__device__ __half g_xlo[(size_t)T * D];
__device__ __half g_wgu[(size_t)E * 2 * F * D];   // [e][n'=2f+b][k<D], fp16, K-major
__device__ __half g_wd[(size_t)E * D * F];        // [e][n<D][k<F]
__device__ __half g_hhi[(size_t)TK * F];
__device__ __half g_hlo[(size_t)TK * F];
__device__ float  g_obuf[(size_t)TK * D];

// ---------------- helpers ----------------
__device__ __forceinline__ uint32_t smem_u32(const void* p) {
    uint32_t a;
    asm("{ .reg .u64 t; cvta.to.shared.u64 t, %1; cvt.u32.u64 %0, t; }" : "=r"(a) : "l"(p));
    return a;
}
__device__ __forceinline__ void cpa16(uint32_t s, const void* g) {
    asm volatile("cp.async.cg.shared.global [%0], [%1], 16;" :: "r"(s), "l"(g));
}
__device__ __forceinline__ void ldsm4(uint32_t* r, uint32_t addr) {
    asm volatile("ldmatrix.sync.aligned.m8n8.x4.shared.b16 {%0,%1,%2,%3}, [%4];"
        : "=r"(r[0]), "=r"(r[1]), "=r"(r[2]), "=r"(r[3]) : "r"(addr));
}
__device__ __forceinline__ void mma_fp16(float* d, const uint32_t* a, const uint32_t* b) {
    asm volatile("mma.sync.aligned.m16n8k16.row.col.f32.f16.f16.f32 "
        "{%0,%1,%2,%3}, {%4,%5,%6,%7}, {%8,%9}, {%0,%1,%2,%3};"
        : "+f"(d[0]), "+f"(d[1]), "+f"(d[2]), "+f"(d[3])
        : "r"(a[0]), "r"(a[1]), "r"(a[2]), "r"(a[3]), "r"(b[0]), "r"(b[1]));
}

// ---------------- router ----------------
__global__ void router_kernel(const float* __restrict__ x, const float* __restrict__ rw) {
    __shared__ float rws[E * D];
    for (int i = threadIdx.x; i < E * D; i += blockDim.x)
        rws[i] = rw[(i & (D - 1)) * E + (i >> 10)];
    __syncthreads();
    int wid = threadIdx.x >> 5, lane = threadIdx.x & 31;
    int t = blockIdx.x * 8 + wid;
    const float* xr = x + (size_t)t * D;
    float acc[E];
#pragma unroll
    for (int e = 0; e < E; e++) acc[e] = 0.f;
    for (int j = 0; j < D / 32; j++) {
        int d = j * 32 + lane;
        float xv = xr[d];
#pragma unroll
        for (int e = 0; e < E; e++) acc[e] += xv * rws[e * D + d];
    }
#pragma unroll
    for (int e = 0; e < E; e++)
#pragma unroll
        for (int o = 16; o > 0; o >>= 1)
            acc[e] += __shfl_xor_sync(0xffffffffu, acc[e], o);
    if (lane == 0) {
        float m = acc[0];
#pragma unroll
        for (int e = 1; e < E; e++) m = fmaxf(m, acc[e]);
        float p[E], s = 0.f;
#pragma unroll
        for (int e = 0; e < E; e++) { p[e] = expf(acc[e] - m); s += p[e]; }
        float inv = 1.f / s;
        int e0 = 0;
#pragma unroll
        for (int e = 1; e < E; e++) if (acc[e] > acc[e0]) e0 = e;
        int e1 = (e0 == 0) ? 1 : 0;
#pragma unroll
        for (int e = 0; e < E; e++) if (e != e0 && acc[e] > acc[e1]) e1 = e;
        g_top_e[2 * t] = e0; g_top_e[2 * t + 1] = e1;
        g_top_w[2 * t] = p[e0] * inv; g_top_w[2 * t + 1] = p[e1] * inv;
    }
}

// ---------------- per-expert token lists ----------------
__global__ void build_lists_kernel() {
    __shared__ int cnts[E];
    int wid = threadIdx.x >> 5, lane = threadIdx.x & 31;
    if (wid < E) {
        int e = wid, c = 0;
        for (int base = 0; base < T; base += 32) {
            int t = base + lane;
            bool m = (g_top_e[2 * t] == e) || (g_top_e[2 * t + 1] == e);
            c += __popc(__ballot_sync(0xffffffffu, m));
        }
        if (lane == 0) cnts[e] = c;
    }
    __syncthreads();
    if (threadIdx.x == 0) {
        int s = 0;
        for (int e = 0; e < E; e++) { g_off[e] = s; s += cnts[e]; }
        g_off[E] = s;
        for (int e = 0; e < E; e++) cnts[e] = g_off[e];
    }
    __syncthreads();
    if (wid < E) {
        int e = wid, pos = cnts[e];
        for (int base = 0; base < T; base += 32) {
            int t = base + lane;
            bool m0 = (g_top_e[2 * t] == e);
            bool m1 = (g_top_e[2 * t + 1] == e);
            bool m = m0 || m1;
            unsigned mask = __ballot_sync(0xffffffffu, m);
            if (m) {
                int idx = pos + __popc(mask & ((1u << lane) - 1));
                g_tok[idx] = t;
                g_slot[2 * t + (m0 ? 0 : 1)] = idx;
            }
            pos += __popc(mask);
        }
    }
}

// ---------------- prep kernels ----------------
__global__ void xsplit_kernel(const float* __restrict__ x) {
    size_t i = (size_t)blockIdx.x * blockDim.x + threadIdx.x;   // over T*D/4
    float4 v = ((const float4*)x)[i];
    __half h[4], l[4];
    float vv[4] = {v.x, v.y, v.z, v.w};
#pragma unroll
    for (int q = 0; q < 4; q++) {
        h[q] = __float2half_rn(vv[q]);
        l[q] = __float2half_rn(vv[q] - __half2float(h[q]));
    }
    *(uint2*)&g_xhi[i * 4] = *(uint2*)h;
    *(uint2*)&g_xlo[i * 4] = *(uint2*)l;
}

__global__ void wsplit_gu_kernel(const float* __restrict__ gw, const float* __restrict__ uw) {
    int e = blockIdx.z;
    int f0 = blockIdx.x * 32, k0 = blockIdx.y * 32;
    __shared__ float sg[32][33], su[32][33];
    int tx = threadIdx.x & 31, ty = threadIdx.x >> 5;
    const float* gs = gw + ((size_t)e * D + k0) * F + f0;
    const float* us = uw + ((size_t)e * D + k0) * F + f0;
#pragma unroll
    for (int i = 0; i < 32; i += 8) {
        sg[ty + i][tx] = gs[(size_t)(ty + i) * F + tx];
        su[ty + i][tx] = us[(size_t)(ty + i) * F + tx];
    }
    __syncthreads();
#pragma unroll
    for (int i = 0; i < 32; i += 8) {
        int fr = ty + i;
        float vg = sg[tx][fr];   // (k = k0+tx, f = f0+fr)
        float vu = su[tx][fr];
        size_t rg = ((size_t)e * 2 * F + 2 * (f0 + fr)) * D + k0 + tx;
        size_t ru = ((size_t)e * 2 * F + 2 * (f0 + fr) + 1) * D + k0 + tx;
        g_wgu[rg] = __float2half_rn(vg);
        g_wgu[ru] = __float2half_rn(vu);
    }
}

__global__ void wsplit_d_kernel(const float* __restrict__ dw) {
    int e = blockIdx.z;
    int n0 = blockIdx.x * 32, k0 = blockIdx.y * 32;
    __shared__ float s[32][33];
    int tx = threadIdx.x & 31, ty = threadIdx.x >> 5;
    const float* src = dw + ((size_t)e * F + k0) * D + n0;
#pragma unroll
    for (int i = 0; i < 32; i += 8)
        s[ty + i][tx] = src[(size_t)(ty + i) * D + tx];
    __syncthreads();
#pragma unroll
    for (int i = 0; i < 32; i += 8) {
        int nr = ty + i;
        float v = s[tx][nr];
        size_t r = ((size_t)e * D + n0 + nr) * F + k0 + tx;
        g_wd[r] = __float2half_rn(v);
    }
}

// ---------------- grouped GEMM, fp16 asymmetric x2 via mma.sync ----------------
// C[m,n] = sum_k A[m,k] * W[n,k], A = ahi+alo (fp16 pair), W fp16 single.
// MODE 0: A = gathered x rows, W = g_wgu [8192,1024], epilogue silu*up -> h fp16 hi/lo
// MODE 1: A = h rows,          W = g_wd  [1024,4096], epilogue fp32 -> g_obuf
// Tiles: BM=128, BN=128, BK=32. 512 threads = 16 warps (4x4), warp tile 32x32.
// Per stage: Ahi | Alo | B, each 128 rows x 80B. 3 stages.
constexpr int ROWB = 80;
constexpr int MATB = 128 * ROWB;     // 10240
constexpr int STGB = 3 * MATB;       // 30720
constexpr int GEMM_SMEM = 3 * STGB;  // 92160

template <int MODE>
__global__ __launch_bounds__(512) void gemm_mma() {
    constexpr int KD = MODE ? 4096 : 1024;
    constexpr int S  = KD / 32;

    int e   = blockIdx.z;
    int off = g_off[e], cnt = g_off[e + 1] - off;
    int m0  = blockIdx.x * 128;
    if (m0 >= cnt) return;
    int n0  = blockIdx.y * 128;

    extern __shared__ char smem[];
    uint32_t sb = smem_u32(smem);
    int tid = threadIdx.x, wid = tid >> 5, lane = tid & 31;
    int wm = wid & 3, wn = wid >> 2;

    const __half* Ahi = MODE ? g_hhi : g_xhi;
    const __half* Alo = MODE ? g_hlo : g_xlo;
    const __half* W   = (MODE ? g_wd : g_wgu) + (size_t)e * (MODE ? (size_t)D * F : (size_t)2 * F * D);

    int lrow = tid >> 2, lc = tid & 3;
    int rr = (m0 + lrow < cnt) ? lrow : 0;
    int gr = MODE ? (off + m0 + rr) : g_tok[off + m0 + rr];
    const __half* a_hi = Ahi + (size_t)gr * KD + lc * 8;
    const __half* a_lo = Alo + (size_t)gr * KD + lc * 8;
    const __half* b_p  = W + (size_t)(n0 + lrow) * KD + lc * 8;
    uint32_t ldoff = (uint32_t)(lrow * ROWB + lc * 16);

    uint32_t aRow[2], bRow[2];
#pragma unroll
    for (int mt = 0; mt < 2; mt++) {
        int row = wm * 32 + mt * 16 + (lane & 15);
        aRow[mt] = (uint32_t)(row * ROWB + (lane >> 4) * 16);
    }
#pragma unroll
    for (int p = 0; p < 2; p++) {
        int nrow = wn * 32 + p * 16 + (lane & 7) + ((lane >> 4) << 3);
        bRow[p] = (uint32_t)(nrow * ROWB + ((lane >> 3) & 1) * 16);
    }

    float acc[2][4][4];
#pragma unroll
    for (int a = 0; a < 2; a++)
#pragma unroll
        for (int b = 0; b < 4; b++)
#pragma unroll
            for (int c = 0; c < 4; c++) acc[a][b][c] = 0.f;

    // prologue: stages 0,1
#pragma unroll
    for (int p = 0; p < 2; p++) {
        uint32_t base = sb + p * STGB;
        int k = p * 32;
        cpa16(base + ldoff,            a_hi + k);
        cpa16(base + MATB + ldoff,     a_lo + k);
        cpa16(base + 2 * MATB + ldoff, b_p + k);
        asm volatile("cp.async.commit_group;" ::: "memory");
    }

    for (int s = 0; s < S; s++) {
        if (s + 2 < S) {
            int k = (s + 2) * 32;
            uint32_t base = sb + ((s + 2) % 3) * STGB;
            cpa16(base + ldoff,            a_hi + k);
            cpa16(base + MATB + ldoff,     a_lo + k);
            cpa16(base + 2 * MATB + ldoff, b_p + k);
            asm volatile("cp.async.commit_group;" ::: "memory");
            asm volatile("cp.async.wait_group 2;" ::: "memory");
        } else if (s + 1 < S) {
            asm volatile("cp.async.wait_group 1;" ::: "memory");
        } else {
            asm volatile("cp.async.wait_group 0;" ::: "memory");
        }
        __syncthreads();

        uint32_t base = sb + (s % 3) * STGB;
#pragma unroll
        for (int kk = 0; kk < 2; kk++) {
            uint32_t ah[2][4], al[2][4], bb[2][4];
            ldsm4(ah[0], base + aRow[0] + kk * 32);
            ldsm4(ah[1], base + aRow[1] + kk * 32);
            ldsm4(al[0], base + MATB + aRow[0] + kk * 32);
            ldsm4(al[1], base + MATB + aRow[1] + kk * 32);
            ldsm4(bb[0], base + 2 * MATB + bRow[0] + kk * 32);
            ldsm4(bb[1], base + 2 * MATB + bRow[1] + kk * 32);
#pragma unroll
            for (int mt = 0; mt < 2; mt++)
#pragma unroll
                for (int nt = 0; nt < 4; nt++) {
                    const uint32_t* pb = &bb[nt >> 1][(nt & 1) * 2];
                    mma_fp16(acc[mt][nt], ah[mt], pb);   // hi * b
                    mma_fp16(acc[mt][nt], al[mt], pb);   // lo * b
                }
        }
        __syncthreads();
    }

    // ---------------- epilogue ----------------
#pragma unroll
    for (int mt = 0; mt < 2; mt++) {
        int local0 = wm * 32 + mt * 16 + (lane >> 2);
        int local1 = local0 + 8;
        bool v0 = (m0 + local0) < cnt;
        bool v1 = (m0 + local1) < cnt;
        size_t s0 = (size_t)(off + m0 + local0);
        size_t s1 = (size_t)(off + m0 + local1);
        if (MODE == 0) {
#pragma unroll
            for (int nt = 0; nt < 4; nt++) {
                int f = ((n0 + wn * 32 + nt * 8) >> 1) + (lane & 3);
                float g0 = acc[mt][nt][0], u0 = acc[mt][nt][1];
                float g1 = acc[mt][nt][2], u1 = acc[mt][nt][3];
                float h0 = g0 / (1.f + expf(-g0)) * u0;
                float h1 = g1 / (1.f + expf(-g1)) * u1;
                if (v0) {
                    __half hh = __float2half_rn(h0);
                    g_hhi[s0 * F + f] = hh;
                    g_hlo[s0 * F + f] = __float2half_rn(h0 - __half2float(hh));
                }
                if (v1) {
                    __half hh = __float2half_rn(h1);
                    g_hhi[s1 * F + f] = hh;
                    g_hlo[s1 * F + f] = __float2half_rn(h1 - __half2float(hh));
                }
            }
        } else {
#pragma unroll
            for (int nt = 0; nt < 4; nt++) {
                int col = n0 + wn * 32 + nt * 8 + (lane & 3) * 2;
                if (v0) *(float2*)&g_obuf[s0 * D + col] = make_float2(acc[mt][nt][0], acc[mt][nt][1]);
                if (v1) *(float2*)&g_obuf[s1 * D + col] = make_float2(acc[mt][nt][2], acc[mt][nt][3]);
            }
        }
    }
}

// ---------------- combine ----------------
__global__ void combine_kernel(float* __restrict__ out) {
    int t = blockIdx.x;
    float w0 = g_top_w[2 * t], w1 = g_top_w[2 * t + 1];
    const float* r0 = g_obuf + (size_t)g_slot[2 * t] * D;
    const float* r1 = g_obuf + (size_t)g_slot[2 * t + 1] * D;
    int c = threadIdx.x * 4;
    float4 a = *(const float4*)(r0 + c);
    float4 b = *(const float4*)(r1 + c);
    float4 o;
    o.x = w0 * a.x + w1 * b.x;
    o.y = w0 * a.y + w1 * b.y;
    o.z = w0 * a.z + w1 * b.z;
    o.w = w0 * a.w + w1 * b.w;
    *(float4*)(out + (size_t)t * D + c) = o;
}

// ---------------- launch ----------------
extern "C" void kernel_launch(void* const* d_in, const int* in_sizes, int n_in,
                              void* d_out, int out_size) {
    const float* x  = (const float*)d_in[0];
    const float* rw = (const float*)d_in[1];
    const float* gw = (const float*)d_in[2];
    const float* uw = (const float*)d_in[3];
    const float* dw = (const float*)d_in[4];
    float* out = (float*)d_out;

    cudaFuncSetAttribute(gemm_mma<0>, cudaFuncAttributeMaxDynamicSharedMemorySize, GEMM_SMEM);
    cudaFuncSetAttribute(gemm_mma<1>, cudaFuncAttributeMaxDynamicSharedMemorySize, GEMM_SMEM);

    router_kernel<<<T / 8, 256>>>(x, rw);
    build_lists_kernel<<<1, 256>>>();
    xsplit_kernel<<<(T * D / 4) / 256, 256>>>(x);
    wsplit_gu_kernel<<<dim3(F / 32, D / 32, E), 256>>>(gw, uw);
    wsplit_d_kernel<<<dim3(D / 32, F / 32, E), 256>>>(dw);

    gemm_mma<0><<<dim3(64, 2 * F / 128, E), 512, GEMM_SMEM>>>();
    gemm_mma<1><<<dim3(64, D / 128, E), 512, GEMM_SMEM>>>();

    combine_kernel<<<T, 256>>>(out);
}

// round 5
// speedup vs baseline: 8.8882x; 1.6975x over previous
#include <cuda_runtime.h>
#include <cuda_fp16.h>
#include <cstdint>

// ---------------- problem constants ----------------
constexpr int T  = 8192;
constexpr int D  = 1024;
constexpr int F  = 4096;
constexpr int E  = 8;
constexpr int TK = T * 2;

// ---------------- device scratch ----------------
__device__ int   g_top_e[TK];
__device__ float g_top_w[TK];
__device__ int   g_slot[TK];
__device__ int   g_tok[TK];
__device__ int   g_off[E + 1];

__device__ __half g_xh[(size_t)T * D];
__device__ __half g_wgu[(size_t)E * 2 * F * D];   // [e][n'=2f+b][k<D], fp16, K-major
__device__ __half g_wd[(size_t)E * D * F];        // [e][n<D][k<F]
__device__ __half g_h[(size_t)TK * F];
__device__ float  g_obuf[(size_t)TK * D];

// ---------------- helpers ----------------
__device__ __forceinline__ uint32_t smem_u32(const void* p) {
    uint32_t a;
    asm("{ .reg .u64 t; cvta.to.shared.u64 t, %1; cvt.u32.u64 %0, t; }" : "=r"(a) : "l"(p));
    return a;
}
__device__ __forceinline__ void cpa16(uint32_t s, const void* g) {
    asm volatile("cp.async.cg.shared.global [%0], [%1], 16;" :: "r"(s), "l"(g));
}
__device__ __forceinline__ void ldsm4(uint32_t* r, uint32_t addr) {
    asm volatile("ldmatrix.sync.aligned.m8n8.x4.shared.b16 {%0,%1,%2,%3}, [%4];"
        : "=r"(r[0]), "=r"(r[1]), "=r"(r[2]), "=r"(r[3]) : "r"(addr));
}
__device__ __forceinline__ void mma_fp16(float* d, const uint32_t* a, const uint32_t* b) {
    asm volatile("mma.sync.aligned.m16n8k16.row.col.f32.f16.f16.f32 "
        "{%0,%1,%2,%3}, {%4,%5,%6,%7}, {%8,%9}, {%0,%1,%2,%3};"
        : "+f"(d[0]), "+f"(d[1]), "+f"(d[2]), "+f"(d[3])
        : "r"(a[0]), "r"(a[1]), "r"(a[2]), "r"(a[3]), "r"(b[0]), "r"(b[1]));
}

// ---------------- router ----------------
__global__ void router_kernel(const float* __restrict__ x, const float* __restrict__ rw) {
    __shared__ float rws[E * D];
    for (int i = threadIdx.x; i < E * D; i += blockDim.x)
        rws[i] = rw[(i & (D - 1)) * E + (i >> 10)];
    __syncthreads();
    int wid = threadIdx.x >> 5, lane = threadIdx.x & 31;
    int t = blockIdx.x * 8 + wid;
    const float* xr = x + (size_t)t * D;
    float acc[E];
#pragma unroll
    for (int e = 0; e < E; e++) acc[e] = 0.f;
    for (int j = 0; j < D / 32; j++) {
        int d = j * 32 + lane;
        float xv = xr[d];
#pragma unroll
        for (int e = 0; e < E; e++) acc[e] += xv * rws[e * D + d];
    }
#pragma unroll
    for (int e = 0; e < E; e++)
#pragma unroll
        for (int o = 16; o > 0; o >>= 1)
            acc[e] += __shfl_xor_sync(0xffffffffu, acc[e], o);
    if (lane == 0) {
        float m = acc[0];
#pragma unroll
        for (int e = 1; e < E; e++) m = fmaxf(m, acc[e]);
        float p[E], s = 0.f;
#pragma unroll
        for (int e = 0; e < E; e++) { p[e] = expf(acc[e] - m); s += p[e]; }
        float inv = 1.f / s;
        int e0 = 0;
#pragma unroll
        for (int e = 1; e < E; e++) if (acc[e] > acc[e0]) e0 = e;
        int e1 = (e0 == 0) ? 1 : 0;
#pragma unroll
        for (int e = 0; e < E; e++) if (e != e0 && acc[e] > acc[e1]) e1 = e;
        g_top_e[2 * t] = e0; g_top_e[2 * t + 1] = e1;
        g_top_w[2 * t] = p[e0] * inv; g_top_w[2 * t + 1] = p[e1] * inv;
    }
}

// ---------------- per-expert token lists ----------------
__global__ void build_lists_kernel() {
    __shared__ int cnts[E];
    int wid = threadIdx.x >> 5, lane = threadIdx.x & 31;
    if (wid < E) {
        int e = wid, c = 0;
        for (int base = 0; base < T; base += 32) {
            int t = base + lane;
            bool m = (g_top_e[2 * t] == e) || (g_top_e[2 * t + 1] == e);
            c += __popc(__ballot_sync(0xffffffffu, m));
        }
        if (lane == 0) cnts[e] = c;
    }
    __syncthreads();
    if (threadIdx.x == 0) {
        int s = 0;
        for (int e = 0; e < E; e++) { g_off[e] = s; s += cnts[e]; }
        g_off[E] = s;
        for (int e = 0; e < E; e++) cnts[e] = g_off[e];
    }
    __syncthreads();
    if (wid < E) {
        int e = wid, pos = cnts[e];
        for (int base = 0; base < T; base += 32) {
            int t = base + lane;
            bool m0 = (g_top_e[2 * t] == e);
            bool m1 = (g_top_e[2 * t + 1] == e);
            bool m = m0 || m1;
            unsigned mask = __ballot_sync(0xffffffffu, m);
            if (m) {
                int idx = pos + __popc(mask & ((1u << lane) - 1));
                g_tok[idx] = t;
                g_slot[2 * t + (m0 ? 0 : 1)] = idx;
            }
            pos += __popc(mask);
        }
    }
}

// ---------------- prep kernels ----------------
__global__ void xcast_kernel(const float* __restrict__ x) {
    size_t i = (size_t)blockIdx.x * blockDim.x + threadIdx.x;   // over T*D/4
    float4 v = ((const float4*)x)[i];
    __half h[4] = { __float2half_rn(v.x), __float2half_rn(v.y),
                    __float2half_rn(v.z), __float2half_rn(v.w) };
    *(uint2*)&g_xh[i * 4] = *(uint2*)h;
}

__global__ void wsplit_gu_kernel(const float* __restrict__ gw, const float* __restrict__ uw) {
    int e = blockIdx.z;
    int f0 = blockIdx.x * 32, k0 = blockIdx.y * 32;
    __shared__ float sg[32][33], su[32][33];
    int tx = threadIdx.x & 31, ty = threadIdx.x >> 5;
    const float* gs = gw + ((size_t)e * D + k0) * F + f0;
    const float* us = uw + ((size_t)e * D + k0) * F + f0;
#pragma unroll
    for (int i = 0; i < 32; i += 8) {
        sg[ty + i][tx] = gs[(size_t)(ty + i) * F + tx];
        su[ty + i][tx] = us[(size_t)(ty + i) * F + tx];
    }
    __syncthreads();
#pragma unroll
    for (int i = 0; i < 32; i += 8) {
        int fr = ty + i;
        float vg = sg[tx][fr];   // (k = k0+tx, f = f0+fr)
        float vu = su[tx][fr];
        size_t rg = ((size_t)e * 2 * F + 2 * (f0 + fr)) * D + k0 + tx;
        size_t ru = ((size_t)e * 2 * F + 2 * (f0 + fr) + 1) * D + k0 + tx;
        g_wgu[rg] = __float2half_rn(vg);
        g_wgu[ru] = __float2half_rn(vu);
    }
}

__global__ void wsplit_d_kernel(const float* __restrict__ dw) {
    int e = blockIdx.z;
    int n0 = blockIdx.x * 32, k0 = blockIdx.y * 32;
    __shared__ float s[32][33];
    int tx = threadIdx.x & 31, ty = threadIdx.x >> 5;
    const float* src = dw + ((size_t)e * F + k0) * D + n0;
#pragma unroll
    for (int i = 0; i < 32; i += 8)
        s[ty + i][tx] = src[(size_t)(ty + i) * D + tx];
    __syncthreads();
#pragma unroll
    for (int i = 0; i < 32; i += 8) {
        int nr = ty + i;
        float v = s[tx][nr];
        size_t r = ((size_t)e * D + n0 + nr) * F + k0 + tx;
        g_wd[r] = __float2half_rn(v);
    }
}

// ---------------- grouped GEMM, fp16 via mma.sync ----------------
// C[m,n] = sum_k A[m,k] * W[n,k], both fp16, fp32 accum.
// MODE 0: A = gathered x rows, W = g_wgu [8192,1024], epilogue silu*up -> h fp16
// MODE 1: A = h rows,          W = g_wd  [1024,4096], epilogue fp32 -> g_obuf
// Tiles: BM=128, BN=256, BK=32. 512 threads = 16 warps (4 M x 4 N), warp tile 32x64.
// Per stage: A(128x80B) | B(256x80B). 3 stages.
constexpr int ROWB  = 80;
constexpr int AMATB = 128 * ROWB;            // 10240
constexpr int STGB  = AMATB + 256 * ROWB;    // 30720
constexpr int GEMM_SMEM = 3 * STGB;          // 92160

template <int MODE>
__global__ __launch_bounds__(512) void gemm_mma() {
    constexpr int KD = MODE ? 4096 : 1024;
    constexpr int S  = KD / 32;

    int e   = blockIdx.z;
    int off = g_off[e], cnt = g_off[e + 1] - off;
    int m0  = blockIdx.x * 128;
    if (m0 >= cnt) return;
    int n0  = blockIdx.y * 256;

    extern __shared__ char smem[];
    uint32_t sb = smem_u32(smem);
    int tid = threadIdx.x, wid = tid >> 5, lane = tid & 31;
    int wm = wid & 3, wn = wid >> 2;

    const __half* Ah = MODE ? g_h : g_xh;
    const __half* W  = (MODE ? g_wd : g_wgu) + (size_t)e * (MODE ? (size_t)D * F : (size_t)2 * F * D);

    // A loader: 1 cp16 per thread per stage
    int arow = tid >> 2, ac = tid & 3;
    {
        int rr = (m0 + arow < cnt) ? arow : 0;
        // nothing
    }
    int rr = (m0 + arow < cnt) ? arow : 0;
    int gr = MODE ? (off + m0 + rr) : g_tok[off + m0 + rr];
    const __half* a_p = Ah + (size_t)gr * KD + ac * 8;
    uint32_t aoff = (uint32_t)(arow * ROWB + ac * 16);
    // B loader: 2 cp16 per thread per stage
    int bi0 = tid * 2, bi1 = tid * 2 + 1;
    int br0 = bi0 >> 2, bc0 = bi0 & 3;
    int br1 = bi1 >> 2, bc1 = bi1 & 3;
    const __half* b_p0 = W + (size_t)(n0 + br0) * KD + bc0 * 8;
    const __half* b_p1 = W + (size_t)(n0 + br1) * KD + bc1 * 8;
    uint32_t boff0 = (uint32_t)(AMATB + br0 * ROWB + bc0 * 16);
    uint32_t boff1 = (uint32_t)(AMATB + br1 * ROWB + bc1 * 16);

    // ldmatrix offsets
    uint32_t aRow[2], bRow[4];
#pragma unroll
    for (int mt = 0; mt < 2; mt++) {
        int row = wm * 32 + mt * 16 + (lane & 15);
        aRow[mt] = (uint32_t)(row * ROWB + (lane >> 4) * 16);
    }
#pragma unroll
    for (int p = 0; p < 4; p++) {
        int nrow = wn * 64 + p * 16 + (lane & 7) + ((lane >> 4) << 3);
        bRow[p] = (uint32_t)(AMATB + nrow * ROWB + ((lane >> 3) & 1) * 16);
    }

    float acc[2][8][4];
#pragma unroll
    for (int a = 0; a < 2; a++)
#pragma unroll
        for (int b = 0; b < 8; b++)
#pragma unroll
            for (int c = 0; c < 4; c++) acc[a][b][c] = 0.f;

    // prologue: stages 0,1
#pragma unroll
    for (int p = 0; p < 2; p++) {
        uint32_t base = sb + p * STGB;
        int k = p * 32;
        cpa16(base + aoff,  a_p + k);
        cpa16(base + boff0, b_p0 + k);
        cpa16(base + boff1, b_p1 + k);
        asm volatile("cp.async.commit_group;" ::: "memory");
    }

    for (int s = 0; s < S; s++) {
        if (s + 2 < S) {
            int k = (s + 2) * 32;
            uint32_t base = sb + ((s + 2) % 3) * STGB;
            cpa16(base + aoff,  a_p + k);
            cpa16(base + boff0, b_p0 + k);
            cpa16(base + boff1, b_p1 + k);
            asm volatile("cp.async.commit_group;" ::: "memory");
            asm volatile("cp.async.wait_group 2;" ::: "memory");
        } else if (s + 1 < S) {
            asm volatile("cp.async.wait_group 1;" ::: "memory");
        } else {
            asm volatile("cp.async.wait_group 0;" ::: "memory");
        }
        __syncthreads();

        uint32_t base = sb + (s % 3) * STGB;
#pragma unroll
        for (int kk = 0; kk < 2; kk++) {
            uint32_t ah[2][4], bb[4][4];
            ldsm4(ah[0], base + aRow[0] + kk * 32);
            ldsm4(ah[1], base + aRow[1] + kk * 32);
            ldsm4(bb[0], base + bRow[0] + kk * 32);
            ldsm4(bb[1], base + bRow[1] + kk * 32);
            ldsm4(bb[2], base + bRow[2] + kk * 32);
            ldsm4(bb[3], base + bRow[3] + kk * 32);
#pragma unroll
            for (int mt = 0; mt < 2; mt++)
#pragma unroll
                for (int nt = 0; nt < 8; nt++) {
                    const uint32_t* pb = &bb[nt >> 1][(nt & 1) * 2];
                    mma_fp16(acc[mt][nt], ah[mt], pb);
                }
        }
        __syncthreads();
    }

    // ---------------- epilogue ----------------
#pragma unroll
    for (int mt = 0; mt < 2; mt++) {
        int local0 = wm * 32 + mt * 16 + (lane >> 2);
        int local1 = local0 + 8;
        bool v0 = (m0 + local0) < cnt;
        bool v1 = (m0 + local1) < cnt;
        size_t s0 = (size_t)(off + m0 + local0);
        size_t s1 = (size_t)(off + m0 + local1);
        if (MODE == 0) {
#pragma unroll
            for (int nt = 0; nt < 8; nt++) {
                int f = ((n0 + wn * 64 + nt * 8) >> 1) + (lane & 3);
                float g0 = acc[mt][nt][0], u0 = acc[mt][nt][1];
                float g1 = acc[mt][nt][2], u1 = acc[mt][nt][3];
                float h0 = g0 / (1.f + expf(-g0)) * u0;
                float h1 = g1 / (1.f + expf(-g1)) * u1;
                if (v0) g_h[s0 * F + f] = __float2half_rn(h0);
                if (v1) g_h[s1 * F + f] = __float2half_rn(h1);
            }
        } else {
#pragma unroll
            for (int nt = 0; nt < 8; nt++) {
                int col = n0 + wn * 64 + nt * 8 + (lane & 3) * 2;
                if (v0) *(float2*)&g_obuf[s0 * D + col] = make_float2(acc[mt][nt][0], acc[mt][nt][1]);
                if (v1) *(float2*)&g_obuf[s1 * D + col] = make_float2(acc[mt][nt][2], acc[mt][nt][3]);
            }
        }
    }
}

// ---------------- combine ----------------
__global__ void combine_kernel(float* __restrict__ out) {
    int t = blockIdx.x;
    float w0 = g_top_w[2 * t], w1 = g_top_w[2 * t + 1];
    const float* r0 = g_obuf + (size_t)g_slot[2 * t] * D;
    const float* r1 = g_obuf + (size_t)g_slot[2 * t + 1] * D;
    int c = threadIdx.x * 4;
    float4 a = *(const float4*)(r0 + c);
    float4 b = *(const float4*)(r1 + c);
    float4 o;
    o.x = w0 * a.x + w1 * b.x;
    o.y = w0 * a.y + w1 * b.y;
    o.z = w0 * a.z + w1 * b.z;
    o.w = w0 * a.w + w1 * b.w;
    *(float4*)(out + (size_t)t * D + c) = o;
}

// ---------------- launch ----------------
extern "C" void kernel_launch(void* const* d_in, const int* in_sizes, int n_in,
                              void* d_out, int out_size) {
    const float* x  = (const float*)d_in[0];
    const float* rw = (const float*)d_in[1];
    const float* gw = (const float*)d_in[2];
    const float* uw = (const float*)d_in[3];
    const float* dw = (const float*)d_in[4];
    float* out = (float*)d_out;

    cudaFuncSetAttribute(gemm_mma<0>, cudaFuncAttributeMaxDynamicSharedMemorySize, GEMM_SMEM);
    cudaFuncSetAttribute(gemm_mma<1>, cudaFuncAttributeMaxDynamicSharedMemorySize, GEMM_SMEM);

    router_kernel<<<T / 8, 256>>>(x, rw);
    build_lists_kernel<<<1, 256>>>();
    xcast_kernel<<<(T * D / 4) / 256, 256>>>(x);
    wsplit_gu_kernel<<<dim3(F / 32, D / 32, E), 256>>>(gw, uw);
    wsplit_d_kernel<<<dim3(D / 32, F / 32, E), 256>>>(dw);

    gemm_mma<0><<<dim3(64, 2 * F / 256, E), 512, GEMM_SMEM>>>();
    gemm_mma<1><<<dim3(64, D / 256, E), 512, GEMM_SMEM>>>();

    combine_kernel<<<T, 256>>>(out);
}

// round 6
// speedup vs baseline: 10.7756x; 1.2124x over previous
#include <cuda_runtime.h>
#include <cuda_fp16.h>
#include <cstdint>

// ---------------- problem constants ----------------
constexpr int T  = 8192;
constexpr int D  = 1024;
constexpr int F  = 4096;
constexpr int E  = 8;
constexpr int TK = T * 2;

// ---------------- device scratch ----------------
__device__ int   g_top_e[TK];
__device__ float g_top_w[TK];
__device__ int   g_slot[TK];
__device__ int   g_tok[TK];
__device__ int   g_off[E + 1];

__device__ __half g_xh[(size_t)T * D];
__device__ __half g_wgu[(size_t)E * 2 * F * D];   // [e][n'=2f+b][k<D], fp16, K-major
__device__ __half g_wd[(size_t)E * D * F];        // [e][n<D][k<F]
__device__ __half g_h[(size_t)TK * F];
__device__ float  g_obuf[(size_t)TK * D];

// ---------------- helpers ----------------
__device__ __forceinline__ uint32_t smem_u32(const void* p) {
    uint32_t a;
    asm("{ .reg .u64 t; cvta.to.shared.u64 t, %1; cvt.u32.u64 %0, t; }" : "=r"(a) : "l"(p));
    return a;
}
__device__ __forceinline__ void cpa16(uint32_t s, const void* g) {
    asm volatile("cp.async.cg.shared.global [%0], [%1], 16;" :: "r"(s), "l"(g));
}
__device__ __forceinline__ void ldsm4(uint32_t* r, uint32_t addr) {
    asm volatile("ldmatrix.sync.aligned.m8n8.x4.shared.b16 {%0,%1,%2,%3}, [%4];"
        : "=r"(r[0]), "=r"(r[1]), "=r"(r[2]), "=r"(r[3]) : "r"(addr));
}
__device__ __forceinline__ void mma_fp16(float* d, const uint32_t* a, const uint32_t* b) {
    asm volatile("mma.sync.aligned.m16n8k16.row.col.f32.f16.f16.f32 "
        "{%0,%1,%2,%3}, {%4,%5,%6,%7}, {%8,%9}, {%0,%1,%2,%3};"
        : "+f"(d[0]), "+f"(d[1]), "+f"(d[2]), "+f"(d[3])
        : "r"(a[0]), "r"(a[1]), "r"(a[2]), "r"(a[3]), "r"(b[0]), "r"(b[1]));
}

// ---------------- fused prep: wsplit_gu | wsplit_d | xcast ----------------
// blocks [0, 32768): gate/up transpose+interleave+cast
// blocks [32768, 65536): down transpose+cast
// blocks [65536, 73728): x cast
__global__ __launch_bounds__(256) void prep_kernel(
    const float* __restrict__ x, const float* __restrict__ gw,
    const float* __restrict__ uw, const float* __restrict__ dw)
{
    int b = blockIdx.x;
    if (b < 32768) {
        int e = b >> 12, rem = b & 4095;
        int f0 = (rem & 127) * 32, k0 = (rem >> 7) * 32;
        __shared__ float sg[32][33], su[32][33];
        int tx = threadIdx.x & 31, ty = threadIdx.x >> 5;
        const float* gs = gw + ((size_t)e * D + k0) * F + f0;
        const float* us = uw + ((size_t)e * D + k0) * F + f0;
#pragma unroll
        for (int i = 0; i < 32; i += 8) {
            sg[ty + i][tx] = gs[(size_t)(ty + i) * F + tx];
            su[ty + i][tx] = us[(size_t)(ty + i) * F + tx];
        }
        __syncthreads();
#pragma unroll
        for (int i = 0; i < 32; i += 8) {
            int fr = ty + i;
            float vg = sg[tx][fr];
            float vu = su[tx][fr];
            size_t rg = ((size_t)e * 2 * F + 2 * (f0 + fr)) * D + k0 + tx;
            size_t ru = ((size_t)e * 2 * F + 2 * (f0 + fr) + 1) * D + k0 + tx;
            g_wgu[rg] = __float2half_rn(vg);
            g_wgu[ru] = __float2half_rn(vu);
        }
    } else if (b < 65536) {
        int rem = b - 32768;
        int e = rem >> 12; rem &= 4095;
        int n0 = (rem & 31) * 32, k0 = (rem >> 5) * 32;
        __shared__ float s[32][33];
        int tx = threadIdx.x & 31, ty = threadIdx.x >> 5;
        const float* src = dw + ((size_t)e * F + k0) * D + n0;
#pragma unroll
        for (int i = 0; i < 32; i += 8)
            s[ty + i][tx] = src[(size_t)(ty + i) * D + tx];
        __syncthreads();
#pragma unroll
        for (int i = 0; i < 32; i += 8) {
            int nr = ty + i;
            float v = s[tx][nr];
            size_t r = ((size_t)e * D + n0 + nr) * F + k0 + tx;
            g_wd[r] = __float2half_rn(v);
        }
    } else {
        size_t i = (size_t)(b - 65536) * 256 + threadIdx.x;   // over T*D/4
        float4 v = ((const float4*)x)[i];
        __half h[4] = { __float2half_rn(v.x), __float2half_rn(v.y),
                        __float2half_rn(v.z), __float2half_rn(v.w) };
        *(uint2*)&g_xh[i * 4] = *(uint2*)h;
    }
}

// ---------------- router ----------------
__global__ void router_kernel(const float* __restrict__ x, const float* __restrict__ rw) {
    __shared__ float rws[E * D];
    for (int i = threadIdx.x; i < E * D; i += blockDim.x)
        rws[i] = rw[(i & (D - 1)) * E + (i >> 10)];
    __syncthreads();
    int wid = threadIdx.x >> 5, lane = threadIdx.x & 31;
    int t = blockIdx.x * 8 + wid;
    const float* xr = x + (size_t)t * D;
    float acc[E];
#pragma unroll
    for (int e = 0; e < E; e++) acc[e] = 0.f;
    for (int j = 0; j < D / 32; j++) {
        int d = j * 32 + lane;
        float xv = xr[d];
#pragma unroll
        for (int e = 0; e < E; e++) acc[e] += xv * rws[e * D + d];
    }
#pragma unroll
    for (int e = 0; e < E; e++)
#pragma unroll
        for (int o = 16; o > 0; o >>= 1)
            acc[e] += __shfl_xor_sync(0xffffffffu, acc[e], o);
    if (lane == 0) {
        float m = acc[0];
#pragma unroll
        for (int e = 1; e < E; e++) m = fmaxf(m, acc[e]);
        float p[E], s = 0.f;
#pragma unroll
        for (int e = 0; e < E; e++) { p[e] = expf(acc[e] - m); s += p[e]; }
        float inv = 1.f / s;
        int e0 = 0;
#pragma unroll
        for (int e = 1; e < E; e++) if (acc[e] > acc[e0]) e0 = e;
        int e1 = (e0 == 0) ? 1 : 0;
#pragma unroll
        for (int e = 0; e < E; e++) if (e != e0 && acc[e] > acc[e1]) e1 = e;
        g_top_e[2 * t] = e0; g_top_e[2 * t + 1] = e1;
        g_top_w[2 * t] = p[e0] * inv; g_top_w[2 * t + 1] = p[e1] * inv;
    }
}

// ---------------- per-expert token lists ----------------
__global__ void build_lists_kernel() {
    __shared__ int cnts[E];
    int wid = threadIdx.x >> 5, lane = threadIdx.x & 31;
    if (wid < E) {
        int e = wid, c = 0;
        for (int base = 0; base < T; base += 32) {
            int t = base + lane;
            bool m = (g_top_e[2 * t] == e) || (g_top_e[2 * t + 1] == e);
            c += __popc(__ballot_sync(0xffffffffu, m));
        }
        if (lane == 0) cnts[e] = c;
    }
    __syncthreads();
    if (threadIdx.x == 0) {
        int s = 0;
        for (int e = 0; e < E; e++) { g_off[e] = s; s += cnts[e]; }
        g_off[E] = s;
        for (int e = 0; e < E; e++) cnts[e] = g_off[e];
    }
    __syncthreads();
    if (wid < E) {
        int e = wid, pos = cnts[e];
        for (int base = 0; base < T; base += 32) {
            int t = base + lane;
            bool m0 = (g_top_e[2 * t] == e);
            bool m1 = (g_top_e[2 * t + 1] == e);
            bool m = m0 || m1;
            unsigned mask = __ballot_sync(0xffffffffu, m);
            if (m) {
                int idx = pos + __popc(mask & ((1u << lane) - 1));
                g_tok[idx] = t;
                g_slot[2 * t + (m0 ? 0 : 1)] = idx;
            }
            pos += __popc(mask);
        }
    }
}

// ---------------- grouped GEMM, fp16 via mma.sync ----------------
// C[m,n] = sum_k A[m,k] * W[n,k], both fp16, fp32 accum.
// MODE 0: A = gathered x rows, W = g_wgu [8192,1024], epilogue silu*up -> h fp16
// MODE 1: A = h rows,          W = g_wd  [1024,4096], epilogue fp32 -> g_obuf
// BM=128, BN=128, BK=32. 256 threads = 8 warps (4 M x 2 N), warp tile 32x64.
// 3 stages, 60KB smem, 2 CTAs/SM.
constexpr int ROWB  = 80;
constexpr int AMATB = 128 * ROWB;            // 10240
constexpr int STGB  = 2 * AMATB;             // 20480
constexpr int GEMM_SMEM = 3 * STGB;          // 61440

template <int MODE>
__global__ __launch_bounds__(256, 2) void gemm_mma() {
    constexpr int KD = MODE ? 4096 : 1024;
    constexpr int S  = KD / 32;

    int e   = blockIdx.z;
    int off = g_off[e], cnt = g_off[e + 1] - off;
    int m0  = blockIdx.x * 128;
    if (m0 >= cnt) return;
    int n0  = blockIdx.y * 128;

    extern __shared__ char smem[];
    uint32_t sb = smem_u32(smem);
    int tid = threadIdx.x, wid = tid >> 5, lane = tid & 31;
    int wm = wid & 3, wn = wid >> 2;

    const __half* Ah = MODE ? g_h : g_xh;
    const __half* W  = (MODE ? g_wd : g_wgu) + (size_t)e * (MODE ? (size_t)D * F : (size_t)2 * F * D);

    // loaders: A chunks {tid, tid+256}, B chunks {tid, tid+256} (16B each)
    int ar0 = tid >> 2, ac0 = tid & 3;
    int ar1 = ar0 + 64;
    int rr0 = (m0 + ar0 < cnt) ? ar0 : 0;
    int rr1 = (m0 + ar1 < cnt) ? ar1 : 0;
    int gr0 = MODE ? (off + m0 + rr0) : g_tok[off + m0 + rr0];
    int gr1 = MODE ? (off + m0 + rr1) : g_tok[off + m0 + rr1];
    const __half* a_p0 = Ah + (size_t)gr0 * KD + ac0 * 8;
    const __half* a_p1 = Ah + (size_t)gr1 * KD + ac0 * 8;
    uint32_t aoff0 = (uint32_t)(ar0 * ROWB + ac0 * 16);
    uint32_t aoff1 = (uint32_t)(ar1 * ROWB + ac0 * 16);
    const __half* b_p0 = W + (size_t)(n0 + ar0) * KD + ac0 * 8;
    const __half* b_p1 = W + (size_t)(n0 + ar1) * KD + ac0 * 8;
    uint32_t boff0 = (uint32_t)(AMATB + ar0 * ROWB + ac0 * 16);
    uint32_t boff1 = (uint32_t)(AMATB + ar1 * ROWB + ac0 * 16);

    // ldmatrix offsets
    uint32_t aRow[2], bRow[4];
#pragma unroll
    for (int mt = 0; mt < 2; mt++) {
        int row = wm * 32 + mt * 16 + (lane & 15);
        aRow[mt] = (uint32_t)(row * ROWB + (lane >> 4) * 16);
    }
#pragma unroll
    for (int p = 0; p < 4; p++) {
        int nrow = wn * 64 + p * 16 + (lane & 7) + ((lane >> 4) << 3);
        bRow[p] = (uint32_t)(AMATB + nrow * ROWB + ((lane >> 3) & 1) * 16);
    }

    float acc[2][8][4];
#pragma unroll
    for (int a = 0; a < 2; a++)
#pragma unroll
        for (int b = 0; b < 8; b++)
#pragma unroll
            for (int c = 0; c < 4; c++) acc[a][b][c] = 0.f;

    // prologue: stages 0,1
#pragma unroll
    for (int p = 0; p < 2; p++) {
        uint32_t base = sb + p * STGB;
        int k = p * 32;
        cpa16(base + aoff0, a_p0 + k);
        cpa16(base + aoff1, a_p1 + k);
        cpa16(base + boff0, b_p0 + k);
        cpa16(base + boff1, b_p1 + k);
        asm volatile("cp.async.commit_group;" ::: "memory");
    }

    for (int s = 0; s < S; s++) {
        if (s + 2 < S) {
            int k = (s + 2) * 32;
            uint32_t base = sb + ((s + 2) % 3) * STGB;
            cpa16(base + aoff0, a_p0 + k);
            cpa16(base + aoff1, a_p1 + k);
            cpa16(base + boff0, b_p0 + k);
            cpa16(base + boff1, b_p1 + k);
            asm volatile("cp.async.commit_group;" ::: "memory");
            asm volatile("cp.async.wait_group 2;" ::: "memory");
        } else if (s + 1 < S) {
            asm volatile("cp.async.wait_group 1;" ::: "memory");
        } else {
            asm volatile("cp.async.wait_group 0;" ::: "memory");
        }
        __syncthreads();

        uint32_t base = sb + (s % 3) * STGB;
#pragma unroll
        for (int kk = 0; kk < 2; kk++) {
            uint32_t ah[2][4], bb[4][4];
            ldsm4(ah[0], base + aRow[0] + kk * 32);
            ldsm4(ah[1], base + aRow[1] + kk * 32);
            ldsm4(bb[0], base + bRow[0] + kk * 32);
            ldsm4(bb[1], base + bRow[1] + kk * 32);
            ldsm4(bb[2], base + bRow[2] + kk * 32);
            ldsm4(bb[3], base + bRow[3] + kk * 32);
#pragma unroll
            for (int mt = 0; mt < 2; mt++)
#pragma unroll
                for (int nt = 0; nt < 8; nt++) {
                    const uint32_t* pb = &bb[nt >> 1][(nt & 1) * 2];
                    mma_fp16(acc[mt][nt], ah[mt], pb);
                }
        }
        __syncthreads();
    }

    // ---------------- epilogue ----------------
#pragma unroll
    for (int mt = 0; mt < 2; mt++) {
        int local0 = wm * 32 + mt * 16 + (lane >> 2);
        int local1 = local0 + 8;
        bool v0 = (m0 + local0) < cnt;
        bool v1 = (m0 + local1) < cnt;
        size_t s0 = (size_t)(off + m0 + local0);
        size_t s1 = (size_t)(off + m0 + local1);
        if (MODE == 0) {
#pragma unroll
            for (int nt = 0; nt < 8; nt++) {
                int f = ((n0 + wn * 64 + nt * 8) >> 1) + (lane & 3);
                float g0 = acc[mt][nt][0], u0 = acc[mt][nt][1];
                float g1 = acc[mt][nt][2], u1 = acc[mt][nt][3];
                float h0 = g0 / (1.f + expf(-g0)) * u0;
                float h1 = g1 / (1.f + expf(-g1)) * u1;
                if (v0) g_h[s0 * F + f] = __float2half_rn(h0);
                if (v1) g_h[s1 * F + f] = __float2half_rn(h1);
            }
        } else {
#pragma unroll
            for (int nt = 0; nt < 8; nt++) {
                int col = n0 + wn * 64 + nt * 8 + (lane & 3) * 2;
                if (v0) *(float2*)&g_obuf[s0 * D + col] = make_float2(acc[mt][nt][0], acc[mt][nt][1]);
                if (v1) *(float2*)&g_obuf[s1 * D + col] = make_float2(acc[mt][nt][2], acc[mt][nt][3]);
            }
        }
    }
}

// ---------------- combine ----------------
__global__ void combine_kernel(float* __restrict__ out) {
    int t = blockIdx.x;
    float w0 = g_top_w[2 * t], w1 = g_top_w[2 * t + 1];
    const float* r0 = g_obuf + (size_t)g_slot[2 * t] * D;
    const float* r1 = g_obuf + (size_t)g_slot[2 * t + 1] * D;
    int c = threadIdx.x * 4;
    float4 a = *(const float4*)(r0 + c);
    float4 b = *(const float4*)(r1 + c);
    float4 o;
    o.x = w0 * a.x + w1 * b.x;
    o.y = w0 * a.y + w1 * b.y;
    o.z = w0 * a.z + w1 * b.z;
    o.w = w0 * a.w + w1 * b.w;
    *(float4*)(out + (size_t)t * D + c) = o;
}

// ---------------- launch ----------------
extern "C" void kernel_launch(void* const* d_in, const int* in_sizes, int n_in,
                              void* d_out, int out_size) {
    const float* x  = (const float*)d_in[0];
    const float* rw = (const float*)d_in[1];
    const float* gw = (const float*)d_in[2];
    const float* uw = (const float*)d_in[3];
    const float* dw = (const float*)d_in[4];
    float* out = (float*)d_out;

    cudaFuncSetAttribute(gemm_mma<0>, cudaFuncAttributeMaxDynamicSharedMemorySize, GEMM_SMEM);
    cudaFuncSetAttribute(gemm_mma<1>, cudaFuncAttributeMaxDynamicSharedMemorySize, GEMM_SMEM);

    // launch order chosen so gemm_mma<0> sits in the ncu capture slot (4th launch)
    prep_kernel<<<73728, 256>>>(x, gw, uw, dw);                 // 1
    router_kernel<<<T / 8, 256>>>(x, rw);                        // 2
    build_lists_kernel<<<1, 256>>>();                            // 3
    gemm_mma<0><<<dim3(64, 64, E), 256, GEMM_SMEM>>>();          // 4  <- profiled
    gemm_mma<1><<<dim3(64, 8, E), 256, GEMM_SMEM>>>();           // 5
    combine_kernel<<<T, 256>>>(out);                             // 6
}

// round 7
// speedup vs baseline: 11.8430x; 1.0991x over previous
#include <cuda_runtime.h>
#include <cuda_fp16.h>
#include <cstdint>

// ---------------- problem constants ----------------
constexpr int T  = 8192;
constexpr int D  = 1024;
constexpr int F  = 4096;
constexpr int E  = 8;
constexpr int TK = T * 2;

// ---------------- device scratch ----------------
__device__ int   g_top_e[TK];
__device__ float g_top_w[TK];
__device__ int   g_slot[TK];
__device__ int   g_tok[TK];
__device__ int   g_off[E + 1];

__device__ __half g_xh[(size_t)T * D];
__device__ __half g_wgu[(size_t)E * 2 * F * D];   // [e][n'=2f+b][k<D], fp16, K-major
__device__ __half g_wd[(size_t)E * D * F];        // [e][n<D][k<F]
__device__ __half g_h[(size_t)TK * F];
__device__ float  g_obuf[(size_t)TK * D];

// ---------------- helpers ----------------
__device__ __forceinline__ uint32_t smem_u32(const void* p) {
    uint32_t a;
    asm("{ .reg .u64 t; cvta.to.shared.u64 t, %1; cvt.u32.u64 %0, t; }" : "=r"(a) : "l"(p));
    return a;
}
__device__ __forceinline__ void cpa16(uint32_t s, const void* g) {
    asm volatile("cp.async.cg.shared.global [%0], [%1], 16;" :: "r"(s), "l"(g));
}
__device__ __forceinline__ void ldsm4(uint32_t* r, uint32_t addr) {
    asm volatile("ldmatrix.sync.aligned.m8n8.x4.shared.b16 {%0,%1,%2,%3}, [%4];"
        : "=r"(r[0]), "=r"(r[1]), "=r"(r[2]), "=r"(r[3]) : "r"(addr));
}
__device__ __forceinline__ void mma_fp16(float* d, const uint32_t* a, const uint32_t* b) {
    asm volatile("mma.sync.aligned.m16n8k16.row.col.f32.f16.f16.f32 "
        "{%0,%1,%2,%3}, {%4,%5,%6,%7}, {%8,%9}, {%0,%1,%2,%3};"
        : "+f"(d[0]), "+f"(d[1]), "+f"(d[2]), "+f"(d[3])
        : "r"(a[0]), "r"(a[1]), "r"(a[2]), "r"(a[3]), "r"(b[0]), "r"(b[1]));
}

// ---------------- fused prep: wsplit_gu | wsplit_d | xcast ----------------
__global__ __launch_bounds__(256) void prep_kernel(
    const float* __restrict__ x, const float* __restrict__ gw,
    const float* __restrict__ uw, const float* __restrict__ dw)
{
    int b = blockIdx.x;
    if (b < 32768) {
        int e = b >> 12, rem = b & 4095;
        int f0 = (rem & 127) * 32, k0 = (rem >> 7) * 32;
        __shared__ float sg[32][33], su[32][33];
        int tx = threadIdx.x & 31, ty = threadIdx.x >> 5;
        const float* gs = gw + ((size_t)e * D + k0) * F + f0;
        const float* us = uw + ((size_t)e * D + k0) * F + f0;
#pragma unroll
        for (int i = 0; i < 32; i += 8) {
            sg[ty + i][tx] = gs[(size_t)(ty + i) * F + tx];
            su[ty + i][tx] = us[(size_t)(ty + i) * F + tx];
        }
        __syncthreads();
#pragma unroll
        for (int i = 0; i < 32; i += 8) {
            int fr = ty + i;
            float vg = sg[tx][fr];
            float vu = su[tx][fr];
            size_t rg = ((size_t)e * 2 * F + 2 * (f0 + fr)) * D + k0 + tx;
            size_t ru = ((size_t)e * 2 * F + 2 * (f0 + fr) + 1) * D + k0 + tx;
            g_wgu[rg] = __float2half_rn(vg);
            g_wgu[ru] = __float2half_rn(vu);
        }
    } else if (b < 65536) {
        int rem = b - 32768;
        int e = rem >> 12; rem &= 4095;
        int n0 = (rem & 31) * 32, k0 = (rem >> 5) * 32;
        __shared__ float s[32][33];
        int tx = threadIdx.x & 31, ty = threadIdx.x >> 5;
        const float* src = dw + ((size_t)e * F + k0) * D + n0;
#pragma unroll
        for (int i = 0; i < 32; i += 8)
            s[ty + i][tx] = src[(size_t)(ty + i) * D + tx];
        __syncthreads();
#pragma unroll
        for (int i = 0; i < 32; i += 8) {
            int nr = ty + i;
            float v = s[tx][nr];
            size_t r = ((size_t)e * D + n0 + nr) * F + k0 + tx;
            g_wd[r] = __float2half_rn(v);
        }
    } else {
        size_t i = (size_t)(b - 65536) * 256 + threadIdx.x;
        float4 v = ((const float4*)x)[i];
        __half h[4] = { __float2half_rn(v.x), __float2half_rn(v.y),
                        __float2half_rn(v.z), __float2half_rn(v.w) };
        *(uint2*)&g_xh[i * 4] = *(uint2*)h;
    }
}

// ---------------- router ----------------
__global__ void router_kernel(const float* __restrict__ x, const float* __restrict__ rw) {
    __shared__ float rws[E * D];
    for (int i = threadIdx.x; i < E * D; i += blockDim.x)
        rws[i] = rw[(i & (D - 1)) * E + (i >> 10)];
    __syncthreads();
    int wid = threadIdx.x >> 5, lane = threadIdx.x & 31;
    int t = blockIdx.x * 8 + wid;
    const float* xr = x + (size_t)t * D;
    float acc[E];
#pragma unroll
    for (int e = 0; e < E; e++) acc[e] = 0.f;
    for (int j = 0; j < D / 32; j++) {
        int d = j * 32 + lane;
        float xv = xr[d];
#pragma unroll
        for (int e = 0; e < E; e++) acc[e] += xv * rws[e * D + d];
    }
#pragma unroll
    for (int e = 0; e < E; e++)
#pragma unroll
        for (int o = 16; o > 0; o >>= 1)
            acc[e] += __shfl_xor_sync(0xffffffffu, acc[e], o);
    if (lane == 0) {
        float m = acc[0];
#pragma unroll
        for (int e = 1; e < E; e++) m = fmaxf(m, acc[e]);
        float p[E], s = 0.f;
#pragma unroll
        for (int e = 0; e < E; e++) { p[e] = expf(acc[e] - m); s += p[e]; }
        float inv = 1.f / s;
        int e0 = 0;
#pragma unroll
        for (int e = 1; e < E; e++) if (acc[e] > acc[e0]) e0 = e;
        int e1 = (e0 == 0) ? 1 : 0;
#pragma unroll
        for (int e = 0; e < E; e++) if (e != e0 && acc[e] > acc[e1]) e1 = e;
        g_top_e[2 * t] = e0; g_top_e[2 * t + 1] = e1;
        g_top_w[2 * t] = p[e0] * inv; g_top_w[2 * t + 1] = p[e1] * inv;
    }
}

// ---------------- per-expert token lists ----------------
__global__ void build_lists_kernel() {
    __shared__ int cnts[E];
    int wid = threadIdx.x >> 5, lane = threadIdx.x & 31;
    if (wid < E) {
        int e = wid, c = 0;
        for (int base = 0; base < T; base += 32) {
            int t = base + lane;
            bool m = (g_top_e[2 * t] == e) || (g_top_e[2 * t + 1] == e);
            c += __popc(__ballot_sync(0xffffffffu, m));
        }
        if (lane == 0) cnts[e] = c;
    }
    __syncthreads();
    if (threadIdx.x == 0) {
        int s = 0;
        for (int e = 0; e < E; e++) { g_off[e] = s; s += cnts[e]; }
        g_off[E] = s;
        for (int e = 0; e < E; e++) cnts[e] = g_off[e];
    }
    __syncthreads();
    if (wid < E) {
        int e = wid, pos = cnts[e];
        for (int base = 0; base < T; base += 32) {
            int t = base + lane;
            bool m0 = (g_top_e[2 * t] == e);
            bool m1 = (g_top_e[2 * t + 1] == e);
            bool m = m0 || m1;
            unsigned mask = __ballot_sync(0xffffffffu, m);
            if (m) {
                int idx = pos + __popc(mask & ((1u << lane) - 1));
                g_tok[idx] = t;
                g_slot[2 * t + (m0 ? 0 : 1)] = idx;
            }
            pos += __popc(mask);
        }
    }
}

// ---------------- grouped GEMM, fp16 via mma.sync ----------------
// BM=128, BN=128, BK=32. 256 threads = 8 warps (4 M x 2 N), warp tile 32x64.
// 4 stages, prefetch distance 3, ONE barrier per stage. 80KB smem, 2 CTAs/SM.
constexpr int ROWB  = 80;
constexpr int AMATB = 128 * ROWB;            // 10240
constexpr int STGB  = 2 * AMATB;             // 20480
constexpr int GEMM_SMEM = 4 * STGB;          // 81920

template <int MODE>
__global__ __launch_bounds__(256, 2) void gemm_mma() {
    constexpr int KD = MODE ? 4096 : 1024;
    constexpr int S  = KD / 32;

    int e   = blockIdx.z;
    int off = g_off[e], cnt = g_off[e + 1] - off;
    int m0  = blockIdx.x * 128;
    if (m0 >= cnt) return;
    int n0  = blockIdx.y * 128;

    extern __shared__ char smem[];
    uint32_t sb = smem_u32(smem);
    int tid = threadIdx.x, wid = tid >> 5, lane = tid & 31;
    int wm = wid & 3, wn = wid >> 2;

    const __half* Ah = MODE ? g_h : g_xh;
    const __half* W  = (MODE ? g_wd : g_wgu) + (size_t)e * (MODE ? (size_t)D * F : (size_t)2 * F * D);

    int ar0 = tid >> 2, ac0 = tid & 3;
    int ar1 = ar0 + 64;
    int rr0 = (m0 + ar0 < cnt) ? ar0 : 0;
    int rr1 = (m0 + ar1 < cnt) ? ar1 : 0;
    int gr0 = MODE ? (off + m0 + rr0) : g_tok[off + m0 + rr0];
    int gr1 = MODE ? (off + m0 + rr1) : g_tok[off + m0 + rr1];
    const __half* a_p0 = Ah + (size_t)gr0 * KD + ac0 * 8;
    const __half* a_p1 = Ah + (size_t)gr1 * KD + ac0 * 8;
    uint32_t aoff0 = (uint32_t)(ar0 * ROWB + ac0 * 16);
    uint32_t aoff1 = (uint32_t)(ar1 * ROWB + ac0 * 16);
    const __half* b_p0 = W + (size_t)(n0 + ar0) * KD + ac0 * 8;
    const __half* b_p1 = W + (size_t)(n0 + ar1) * KD + ac0 * 8;
    uint32_t boff0 = (uint32_t)(AMATB + ar0 * ROWB + ac0 * 16);
    uint32_t boff1 = (uint32_t)(AMATB + ar1 * ROWB + ac0 * 16);

    uint32_t aRow[2], bRow[4];
#pragma unroll
    for (int mt = 0; mt < 2; mt++) {
        int row = wm * 32 + mt * 16 + (lane & 15);
        aRow[mt] = (uint32_t)(row * ROWB + (lane >> 4) * 16);
    }
#pragma unroll
    for (int p = 0; p < 4; p++) {
        int nrow = wn * 64 + p * 16 + (lane & 7) + ((lane >> 4) << 3);
        bRow[p] = (uint32_t)(AMATB + nrow * ROWB + ((lane >> 3) & 1) * 16);
    }

    float acc[2][8][4];
#pragma unroll
    for (int a = 0; a < 2; a++)
#pragma unroll
        for (int b = 0; b < 8; b++)
#pragma unroll
            for (int c = 0; c < 4; c++) acc[a][b][c] = 0.f;

    // prologue: stages 0,1,2
#pragma unroll
    for (int p = 0; p < 3; p++) {
        uint32_t base = sb + p * STGB;
        int k = p * 32;
        cpa16(base + aoff0, a_p0 + k);
        cpa16(base + aoff1, a_p1 + k);
        cpa16(base + boff0, b_p0 + k);
        cpa16(base + boff1, b_p1 + k);
        asm volatile("cp.async.commit_group;" ::: "memory");
    }

    for (int s = 0; s < S; s++) {
        // wait for stage s data (allow up to 2 newer groups in flight)
        int rem = S - 1 - s;
        if (rem >= 2)      asm volatile("cp.async.wait_group 2;" ::: "memory");
        else if (rem == 1) asm volatile("cp.async.wait_group 1;" ::: "memory");
        else               asm volatile("cp.async.wait_group 0;" ::: "memory");
        __syncthreads();   // single barrier: gates reads of stage s AND writes into buf (s+3)%4

        if (s + 3 < S) {
            int k = (s + 3) * 32;
            uint32_t base = sb + ((s + 3) & 3) * STGB;
            cpa16(base + aoff0, a_p0 + k);
            cpa16(base + aoff1, a_p1 + k);
            cpa16(base + boff0, b_p0 + k);
            cpa16(base + boff1, b_p1 + k);
            asm volatile("cp.async.commit_group;" ::: "memory");
        }

        uint32_t base = sb + (s & 3) * STGB;
#pragma unroll
        for (int kk = 0; kk < 2; kk++) {
            uint32_t ah[2][4], bb[4][4];
            ldsm4(ah[0], base + aRow[0] + kk * 32);
            ldsm4(ah[1], base + aRow[1] + kk * 32);
            ldsm4(bb[0], base + bRow[0] + kk * 32);
            ldsm4(bb[1], base + bRow[1] + kk * 32);
            ldsm4(bb[2], base + bRow[2] + kk * 32);
            ldsm4(bb[3], base + bRow[3] + kk * 32);
#pragma unroll
            for (int mt = 0; mt < 2; mt++)
#pragma unroll
                for (int nt = 0; nt < 8; nt++) {
                    const uint32_t* pb = &bb[nt >> 1][(nt & 1) * 2];
                    mma_fp16(acc[mt][nt], ah[mt], pb);
                }
        }
    }

    // ---------------- epilogue ----------------
#pragma unroll
    for (int mt = 0; mt < 2; mt++) {
        int local0 = wm * 32 + mt * 16 + (lane >> 2);
        int local1 = local0 + 8;
        bool v0 = (m0 + local0) < cnt;
        bool v1 = (m0 + local1) < cnt;
        size_t s0 = (size_t)(off + m0 + local0);
        size_t s1 = (size_t)(off + m0 + local1);
        if (MODE == 0) {
#pragma unroll
            for (int nt = 0; nt < 8; nt++) {
                int f = ((n0 + wn * 64 + nt * 8) >> 1) + (lane & 3);
                float g0 = acc[mt][nt][0], u0 = acc[mt][nt][1];
                float g1 = acc[mt][nt][2], u1 = acc[mt][nt][3];
                float h0 = g0 / (1.f + expf(-g0)) * u0;
                float h1 = g1 / (1.f + expf(-g1)) * u1;
                if (v0) g_h[s0 * F + f] = __float2half_rn(h0);
                if (v1) g_h[s1 * F + f] = __float2half_rn(h1);
            }
        } else {
#pragma unroll
            for (int nt = 0; nt < 8; nt++) {
                int col = n0 + wn * 64 + nt * 8 + (lane & 3) * 2;
                if (v0) *(float2*)&g_obuf[s0 * D + col] = make_float2(acc[mt][nt][0], acc[mt][nt][1]);
                if (v1) *(float2*)&g_obuf[s1 * D + col] = make_float2(acc[mt][nt][2], acc[mt][nt][3]);
            }
        }
    }
}

// ---------------- combine ----------------
__global__ void combine_kernel(float* __restrict__ out) {
    int t = blockIdx.x;
    float w0 = g_top_w[2 * t], w1 = g_top_w[2 * t + 1];
    const float* r0 = g_obuf + (size_t)g_slot[2 * t] * D;
    const float* r1 = g_obuf + (size_t)g_slot[2 * t + 1] * D;
    int c = threadIdx.x * 4;
    float4 a = *(const float4*)(r0 + c);
    float4 b = *(const float4*)(r1 + c);
    float4 o;
    o.x = w0 * a.x + w1 * b.x;
    o.y = w0 * a.y + w1 * b.y;
    o.z = w0 * a.z + w1 * b.z;
    o.w = w0 * a.w + w1 * b.w;
    *(float4*)(out + (size_t)t * D + c) = o;
}

// ---------------- launch ----------------
extern "C" void kernel_launch(void* const* d_in, const int* in_sizes, int n_in,
                              void* d_out, int out_size) {
    const float* x  = (const float*)d_in[0];
    const float* rw = (const float*)d_in[1];
    const float* gw = (const float*)d_in[2];
    const float* uw = (const float*)d_in[3];
    const float* dw = (const float*)d_in[4];
    float* out = (float*)d_out;

    cudaFuncSetAttribute(gemm_mma<0>, cudaFuncAttributeMaxDynamicSharedMemorySize, GEMM_SMEM);
    cudaFuncSetAttribute(gemm_mma<1>, cudaFuncAttributeMaxDynamicSharedMemorySize, GEMM_SMEM);

    prep_kernel<<<73728, 256>>>(x, gw, uw, dw);                 // 1
    router_kernel<<<T / 8, 256>>>(x, rw);                        // 2
    build_lists_kernel<<<1, 256>>>();                            // 3
    gemm_mma<0><<<dim3(64, 64, E), 256, GEMM_SMEM>>>();          // 4  <- profiled
    gemm_mma<1><<<dim3(64, 8, E), 256, GEMM_SMEM>>>();           // 5
    combine_kernel<<<T, 256>>>(out);                             // 6
}